// round 13
// baseline (speedup 1.0000x reference)
#include <cuda_runtime.h>
#include <cstddef>

#define B_   8
#define C_   256
#define N_   1024      // 32*32 spatial flattened
#define EXP_ 4
#define NN_  (N_*N_)
#define ROWS_ 16       // output rows per fused block

// ---------------- scratch (static device arrays; no runtime alloc) -----------
__device__ float g_dwq[B_*C_*N_];
__device__ float g_dwk[B_*C_*N_];
__device__ float g_dwv[B_*C_*N_];
__device__ float g_q  [B_*C_*N_];
__device__ float g_k  [B_*EXP_*C_*N_];
__device__ float g_v  [B_*C_*N_];
__device__ float g_attn [B_*EXP_*NN_];   // pre-gate attention (post qk*scale)
__device__ float g_out0[B_*C_*N_];       // attn @ v^T before proj conv
__device__ float g_wqT[C_*C_];           // transposed pointwise weights [c][oc]
__device__ float g_wkT[C_*EXP_*C_];
__device__ float g_wvT[C_*C_];

// ---------------- weight transpose: in [OC][256] -> out [256][OC] ------------
__global__ void transpose_w(const float* __restrict__ in, float* __restrict__ out, int OC)
{
    __shared__ float t[32][33];
    int oc0 = blockIdx.x * 32, c0 = blockIdx.y * 32;
    int x = threadIdx.x, y = threadIdx.y;
    for (int i = y; i < 32; i += 8) t[i][x] = in[(size_t)(oc0+i)*C_ + c0 + x];
    __syncthreads();
    for (int i = y; i < 32; i += 8) out[(size_t)(c0+i)*OC + oc0 + x] = t[x][i];
}

// ---------------- K1: fused 3-branch depthwise 3x3 + bias --------------------
__global__ void dw3_kernel(const float* __restrict__ x,
                           const float* __restrict__ wq, const float* __restrict__ bq,
                           const float* __restrict__ wk, const float* __restrict__ bk,
                           const float* __restrict__ wv, const float* __restrict__ bv)
{
    __shared__ float plane[N_];
    int bc = blockIdx.x; int b = bc >> 8, c = bc & 255;
    const float* src = x + ((size_t)(b*C_ + c))*N_;
    int tid = threadIdx.x;
    for (int i = tid; i < N_; i += 256) plane[i] = src[i];
    __syncthreads();
    float wwq[9], wwk[9], wwv[9];
    #pragma unroll
    for (int t = 0; t < 9; t++) { wwq[t]=wq[c*9+t]; wwk[t]=wk[c*9+t]; wwv[t]=wv[c*9+t]; }
    float bbq = bq[c], bbk = bk[c], bbv = bv[c];
    for (int i = tid; i < N_; i += 256) {
        int h = i >> 5, w = i & 31;
        float aq = bbq, ak = bbk, av = bbv;
        #pragma unroll
        for (int ky = 0; ky < 3; ky++) {
            int hh = h + ky - 1; if ((unsigned)hh >= 32u) continue;
            #pragma unroll
            for (int kx = 0; kx < 3; kx++) {
                int ww = w + kx - 1; if ((unsigned)ww >= 32u) continue;
                float in = plane[hh*32 + ww];
                aq += wwq[ky*3+kx]*in; ak += wwk[ky*3+kx]*in; av += wwv[ky*3+kx]*in;
            }
        }
        size_t o = ((size_t)(b*C_ + c))*N_ + i;
        g_dwq[o] = aq; g_dwk[o] = ak; g_dwv[o] = av;
    }
}

// ======== 128x128x16 SGEMM core, 8x8 per thread, both operands K-major =======
__global__ void __launch_bounds__(256,2) gemm128_nn(
    const float* __restrict__ A, size_t aBS, int aShift, int lda,
    const float* __restrict__ B, size_t bBS, int ldb,
    float* __restrict__ C, size_t cBS, int ldc,
    const float* __restrict__ bias, float alpha, int K)
{
    __shared__ float As[16][132];
    __shared__ float Bs[16][132];
    int z = blockIdx.z;
    const float* Ag = A + ((size_t)(z >> aShift))*aBS + blockIdx.y*128;
    const float* Bg = B + (size_t)z*bBS + blockIdx.x*128;
    int tid = threadIdx.x;
    int tx = tid & 15, ty = tid >> 4;
    int lr = tid >> 5, lc = (tid & 31) << 2;

    float4 a0 = *(const float4*)&Ag[(size_t)lr*lda + lc];
    float4 a1 = *(const float4*)&Ag[(size_t)(lr+8)*lda + lc];
    float4 b0 = *(const float4*)&Bg[(size_t)lr*ldb + lc];
    float4 b1 = *(const float4*)&Bg[(size_t)(lr+8)*ldb + lc];

    float acc[8][8] = {};
    for (int k0 = 0; k0 < K; k0 += 16) {
        __syncthreads();
        *(float4*)&As[lr][lc]   = a0;  *(float4*)&As[lr+8][lc] = a1;
        *(float4*)&Bs[lr][lc]   = b0;  *(float4*)&Bs[lr+8][lc] = b1;
        __syncthreads();
        if (k0 + 16 < K) {
            a0 = *(const float4*)&Ag[(size_t)(k0+16+lr)*lda + lc];
            a1 = *(const float4*)&Ag[(size_t)(k0+24+lr)*lda + lc];
            b0 = *(const float4*)&Bg[(size_t)(k0+16+lr)*ldb + lc];
            b1 = *(const float4*)&Bg[(size_t)(k0+24+lr)*ldb + lc];
        }
        #pragma unroll
        for (int kk = 0; kk < 16; kk++) {
            float4 x0 = *(float4*)&As[kk][ty*8];
            float4 x1 = *(float4*)&As[kk][ty*8+4];
            float4 y0 = *(float4*)&Bs[kk][tx*8];
            float4 y1 = *(float4*)&Bs[kk][tx*8+4];
            float ar[8] = {x0.x,x0.y,x0.z,x0.w,x1.x,x1.y,x1.z,x1.w};
            float br[8] = {y0.x,y0.y,y0.z,y0.w,y1.x,y1.y,y1.z,y1.w};
            #pragma unroll
            for (int i = 0; i < 8; i++)
                #pragma unroll
                for (int j = 0; j < 8; j++) acc[i][j] += ar[i]*br[j];
        }
    }
    float* Cg = C + (size_t)z*cBS;
    int mB = blockIdx.y*128 + ty*8, nB = blockIdx.x*128 + tx*8;
    #pragma unroll
    for (int i = 0; i < 8; i++) {
        int m = mB + i;
        float bi = bias ? bias[m] : 0.f;
        float4 o0 = make_float4(acc[i][0]*alpha+bi, acc[i][1]*alpha+bi,
                                acc[i][2]*alpha+bi, acc[i][3]*alpha+bi);
        float4 o1 = make_float4(acc[i][4]*alpha+bi, acc[i][5]*alpha+bi,
                                acc[i][6]*alpha+bi, acc[i][7]*alpha+bi);
        *(float4*)&Cg[(size_t)m*ldc + nB]     = o0;
        *(float4*)&Cg[(size_t)m*ldc + nB + 4] = o1;
    }
}

// ======== 128x128x16 core, both operands K-minor (row-major, K contiguous) ===
__global__ void __launch_bounds__(256,2) gemm128_tt(
    const float* __restrict__ A, size_t aBS, int lda,
    const float* __restrict__ B, size_t bBS, int ldb,
    float* __restrict__ C, size_t cBS, int ldc, int K)
{
    __shared__ float As[16][132];
    __shared__ float Bs[16][132];
    int z = blockIdx.z;
    const float* Ag = A + (size_t)z*aBS + (size_t)(blockIdx.y*128)*lda;
    const float* Bg = B + (size_t)z*bBS + (size_t)(blockIdx.x*128)*ldb;
    int tid = threadIdx.x;
    int tx = tid & 15, ty = tid >> 4;
    int r0 = tid >> 2, c0 = (tid & 3) << 2;

    float4 a0 = *(const float4*)&Ag[(size_t)r0*lda + c0];
    float4 a1 = *(const float4*)&Ag[(size_t)(r0+64)*lda + c0];
    float4 b0 = *(const float4*)&Bg[(size_t)r0*ldb + c0];
    float4 b1 = *(const float4*)&Bg[(size_t)(r0+64)*ldb + c0];

    float acc[8][8] = {};
    for (int k0 = 0; k0 < K; k0 += 16) {
        __syncthreads();
        As[c0+0][r0]=a0.x; As[c0+1][r0]=a0.y; As[c0+2][r0]=a0.z; As[c0+3][r0]=a0.w;
        As[c0+0][r0+64]=a1.x; As[c0+1][r0+64]=a1.y; As[c0+2][r0+64]=a1.z; As[c0+3][r0+64]=a1.w;
        Bs[c0+0][r0]=b0.x; Bs[c0+1][r0]=b0.y; Bs[c0+2][r0]=b0.z; Bs[c0+3][r0]=b0.w;
        Bs[c0+0][r0+64]=b1.x; Bs[c0+1][r0+64]=b1.y; Bs[c0+2][r0+64]=b1.z; Bs[c0+3][r0+64]=b1.w;
        __syncthreads();
        if (k0 + 16 < K) {
            a0 = *(const float4*)&Ag[(size_t)r0*lda + k0+16 + c0];
            a1 = *(const float4*)&Ag[(size_t)(r0+64)*lda + k0+16 + c0];
            b0 = *(const float4*)&Bg[(size_t)r0*ldb + k0+16 + c0];
            b1 = *(const float4*)&Bg[(size_t)(r0+64)*ldb + k0+16 + c0];
        }
        #pragma unroll
        for (int kk = 0; kk < 16; kk++) {
            float4 x0 = *(float4*)&As[kk][ty*8];
            float4 x1 = *(float4*)&As[kk][ty*8+4];
            float4 y0 = *(float4*)&Bs[kk][tx*8];
            float4 y1 = *(float4*)&Bs[kk][tx*8+4];
            float ar[8] = {x0.x,x0.y,x0.z,x0.w,x1.x,x1.y,x1.z,x1.w};
            float br[8] = {y0.x,y0.y,y0.z,y0.w,y1.x,y1.y,y1.z,y1.w};
            #pragma unroll
            for (int i = 0; i < 8; i++)
                #pragma unroll
                for (int j = 0; j < 8; j++) acc[i][j] += ar[i]*br[j];
        }
    }
    float* Cg = C + (size_t)z*cBS;
    int mB = blockIdx.y*128 + ty*8, nB = blockIdx.x*128 + tx*8;
    #pragma unroll
    for (int i = 0; i < 8; i++) {
        int m = mB + i;
        *(float4*)&Cg[(size_t)m*ldc + nB]     = *(float4*)&acc[i][0];
        *(float4*)&Cg[(size_t)m*ldc + nB + 4] = *(float4*)&acc[i][4];
    }
}

// ======= K45: FUSED conv0(4->4)+BN + self-gated softmax + conv1(4->1) ========
// Rolling 3-row windows; one block = 16 output rows of one batch. g_gated is
// never materialized. Dynamic smem: attn window 48KB + gated window 48KB.
__global__ void __launch_bounds__(256) fused_gate_attn1(
    const float* __restrict__ w0,
    const float* __restrict__ gma, const float* __restrict__ bta,
    const float* __restrict__ mu,  const float* __restrict__ var,
    const float* __restrict__ w1,  float* __restrict__ dst)
{
    extern __shared__ float sm[];
    float* attn_s  = sm;                 // [4][3][N_]
    float* gated_s = sm + 4*3*N_;        // [4][3][N_]
    __shared__ float wsm[144];
    __shared__ float w1sm[36];
    __shared__ float redM[8][4];
    __shared__ float redS[8][4];

    int b = blockIdx.y;
    int r0 = blockIdx.x * ROWS_;
    int tid = threadIdx.x;
    int lane = tid & 31, wid = tid >> 5;

    if (tid < 144) wsm[tid] = w0[tid];
    if (tid < 36)  w1sm[tid] = w1[tid];
    float sc[4], sh[4];
    #pragma unroll
    for (int f = 0; f < 4; f++) {
        float inv = rsqrtf(var[f] + 1e-5f);
        sc[f] = gma[f] * inv; sh[f] = bta[f] - mu[f] * sc[f];
    }

    #define SLOT(r)  (((r) + 3072) % 3)
    #define ATT(e,s,m)   attn_s [(((e)*3)+(s))*N_ + (m)]
    #define GAT(f,s,m)   gated_s[(((f)*3)+(s))*N_ + (m)]

    // prologue: load attn rows r0-2, r0-1, r0 (4 channels each, float4)
    for (int rr = r0-2; rr <= r0; rr++) {
        int s = SLOT(rr);
        bool ok = (unsigned)rr < (unsigned)N_;
        #pragma unroll
        for (int e = 0; e < 4; e++) {
            float4 v = ok ? *(const float4*)&g_attn[(((size_t)(b*4+e))*N_ + rr)*N_ + tid*4]
                          : make_float4(0.f,0.f,0.f,0.f);
            *(float4*)&ATT(e, s, tid*4) = v;
        }
    }
    __syncthreads();

    for (int g = r0-1; g <= r0+ROWS_; g++) {
        int s1 = SLOT(g);
        if ((unsigned)g < (unsigned)N_) {
            // --- conv0 + BN for gated row g ---
            int srow[3] = {SLOT(g-1), s1, SLOT(g+1)};
            float acc[4][4] = {};
            #pragma unroll
            for (int e = 0; e < 4; e++) {
                #pragma unroll
                for (int t = 0; t < 9; t++) {
                    int ky = t/3, kx = t%3;
                    float w0r = wsm[(0*4+e)*9+t], w1r = wsm[(1*4+e)*9+t];
                    float w2r = wsm[(2*4+e)*9+t], w3r = wsm[(3*4+e)*9+t];
                    #pragma unroll
                    for (int j = 0; j < 4; j++) {
                        int m = tid + 256*j + kx - 1;
                        float in = ((unsigned)m < (unsigned)N_) ? ATT(e, srow[ky], m) : 0.f;
                        acc[0][j] += w0r*in; acc[1][j] += w1r*in;
                        acc[2][j] += w2r*in; acc[3][j] += w3r*in;
                    }
                }
            }
            #pragma unroll
            for (int f = 0; f < 4; f++)
                #pragma unroll
                for (int j = 0; j < 4; j++) acc[f][j] = acc[f][j]*sc[f] + sh[f];

            // --- softmax over m (all 4 channels at once) ---
            float mx[4];
            #pragma unroll
            for (int f = 0; f < 4; f++)
                mx[f] = fmaxf(fmaxf(acc[f][0], acc[f][1]), fmaxf(acc[f][2], acc[f][3]));
            #pragma unroll
            for (int o = 16; o > 0; o >>= 1)
                #pragma unroll
                for (int f = 0; f < 4; f++)
                    mx[f] = fmaxf(mx[f], __shfl_xor_sync(0xffffffffu, mx[f], o));
            if (lane == 0) { redM[wid][0]=mx[0]; redM[wid][1]=mx[1]; redM[wid][2]=mx[2]; redM[wid][3]=mx[3]; }
            __syncthreads();
            float M[4];
            #pragma unroll
            for (int f = 0; f < 4; f++) {
                float v = redM[0][f];
                #pragma unroll
                for (int w = 1; w < 8; w++) v = fmaxf(v, redM[w][f]);
                M[f] = v;
            }
            float es[4][4], ps[4] = {0.f,0.f,0.f,0.f};
            #pragma unroll
            for (int f = 0; f < 4; f++)
                #pragma unroll
                for (int j = 0; j < 4; j++) { es[f][j] = __expf(acc[f][j] - M[f]); ps[f] += es[f][j]; }
            #pragma unroll
            for (int o = 16; o > 0; o >>= 1)
                #pragma unroll
                for (int f = 0; f < 4; f++)
                    ps[f] += __shfl_xor_sync(0xffffffffu, ps[f], o);
            if (lane == 0) { redS[wid][0]=ps[0]; redS[wid][1]=ps[1]; redS[wid][2]=ps[2]; redS[wid][3]=ps[3]; }
            __syncthreads();
            float invS[4];
            #pragma unroll
            for (int f = 0; f < 4; f++) {
                float v = 0.f;
                #pragma unroll
                for (int w = 0; w < 8; w++) v += redS[w][f];
                invS[f] = 1.f / v;
            }
            // --- gated write ---
            #pragma unroll
            for (int f = 0; f < 4; f++)
                #pragma unroll
                for (int j = 0; j < 4; j++)
                    GAT(f, s1, tid + 256*j) = acc[f][j] * es[f][j] * invS[f];
        } else {
            #pragma unroll
            for (int f = 0; f < 4; f++)
                #pragma unroll
                for (int j = 0; j < 4; j++) GAT(f, s1, tid + 256*j) = 0.f;
        }
        __syncthreads();   // gated row g visible

        // --- attn1 output row n = g-1 ---
        if (g >= r0+1) {
            int n = g-1;
            int trow[3] = {SLOT(n-1), SLOT(n), SLOT(n+1)};
            float acc2[4] = {};
            #pragma unroll
            for (int e = 0; e < 4; e++)
                #pragma unroll
                for (int t = 0; t < 9; t++) {
                    int ky = t/3, kx = t%3;
                    float wv = w1sm[e*9 + t];
                    #pragma unroll
                    for (int j = 0; j < 4; j++) {
                        int m = tid + 256*j + kx - 1;
                        float in = ((unsigned)m < (unsigned)N_) ? GAT(e, trow[ky], m) : 0.f;
                        acc2[j] += wv*in;
                    }
                }
            #pragma unroll
            for (int j = 0; j < 4; j++)
                dst[((size_t)b*N_ + n)*N_ + tid + 256*j] = acc2[j];
        }

        // --- load attn row g+2 into slot SLOT(g+2) (== SLOT(g-1), now free) ---
        if (g < r0+ROWS_) {
            int rr = g+2; int s = SLOT(rr);
            bool ok = (unsigned)rr < (unsigned)N_;
            #pragma unroll
            for (int e = 0; e < 4; e++) {
                float4 v = ok ? *(const float4*)&g_attn[(((size_t)(b*4+e))*N_ + rr)*N_ + tid*4]
                              : make_float4(0.f,0.f,0.f,0.f);
                *(float4*)&ATT(e, s, tid*4) = v;
            }
        }
        __syncthreads();
    }
    #undef SLOT
    #undef ATT
    #undef GAT
}

// ---------------- K7: proj 3x3 conv (256->256, no bias) -> first output ------
__global__ void proj_kernel(const float* __restrict__ pw, float* __restrict__ dst)
{
    __shared__ float inT[8][34*34];
    __shared__ float wT[4][8][9];
    int ocg = blockIdx.x;          // 0..63 (4 oc each)
    int b   = blockIdx.y;
    int tid = threadIdx.x;
    int base34[4];
    #pragma unroll
    for (int i = 0; i < 4; i++) {
        int sp = tid + 256*i; int h = sp >> 5, w = sp & 31;
        base34[i] = h*34 + w;
    }
    float acc[4][4] = {};
    for (int cc = 0; cc < 32; cc++) {
        __syncthreads();
        for (int idx = tid; idx < 8*1156; idx += 256) {
            int ic = idx / 1156, rem = idx % 1156;
            int hh = rem / 34 - 1, ww = rem % 34 - 1;
            float v = 0.f;
            if ((unsigned)hh < 32u && (unsigned)ww < 32u)
                v = g_out0[((size_t)b*C_ + cc*8 + ic)*N_ + hh*32 + ww];
            inT[ic][rem] = v;
        }
        for (int idx = tid; idx < 288; idx += 256) {
            int oc = idx / 72, r2 = idx % 72, ic = r2 / 9, t = r2 % 9;
            wT[oc][ic][t] = pw[((size_t)(ocg*4 + oc)*C_ + cc*8 + ic)*9 + t];
        }
        __syncthreads();
        #pragma unroll
        for (int ic = 0; ic < 8; ic++) {
            #pragma unroll
            for (int t = 0; t < 9; t++) {
                int off = (t/3)*34 + (t%3);
                float w0 = wT[0][ic][t], w1 = wT[1][ic][t];
                float w2 = wT[2][ic][t], w3 = wT[3][ic][t];
                #pragma unroll
                for (int i = 0; i < 4; i++) {
                    float in = inT[ic][base34[i] + off];
                    acc[0][i] += w0*in; acc[1][i] += w1*in;
                    acc[2][i] += w2*in; acc[3][i] += w3*in;
                }
            }
        }
    }
    #pragma unroll
    for (int oc = 0; oc < 4; oc++)
        #pragma unroll
        for (int i = 0; i < 4; i++)
            dst[((size_t)b*C_ + ocg*4 + oc)*N_ + tid + 256*i] = acc[oc][i];
}

// ---------------------------------------------------------------------------
extern "C" void kernel_launch(void* const* d_in, const int* in_sizes, int n_in,
                              void* d_out, int out_size)
{
    const float* x       = (const float*)d_in[0];
    const float* qa_dw_w = (const float*)d_in[1];
    const float* qa_dw_b = (const float*)d_in[2];
    const float* qa_pw_w = (const float*)d_in[3];
    const float* qa_pw_b = (const float*)d_in[4];
    const float* ka_dw_w = (const float*)d_in[5];
    const float* ka_dw_b = (const float*)d_in[6];
    const float* ka_pw_w = (const float*)d_in[7];
    const float* ka_pw_b = (const float*)d_in[8];
    const float* va_dw_w = (const float*)d_in[9];
    const float* va_dw_b = (const float*)d_in[10];
    const float* va_pw_w = (const float*)d_in[11];
    const float* va_pw_b = (const float*)d_in[12];
    const float* attn0_w = (const float*)d_in[13];
    const float* bn_g    = (const float*)d_in[14];
    const float* bn_b    = (const float*)d_in[15];
    const float* bn_m    = (const float*)d_in[16];
    const float* bn_v    = (const float*)d_in[17];
    const float* attn1_w = (const float*)d_in[18];
    const float* proj_w  = (const float*)d_in[19];

    float* out_main = (float*)d_out;                 // [8,256,32,32]
    float* out_attn = out_main + (size_t)B_*C_*N_;   // [8,1,1024,1024]

    void *p_dwq, *p_dwk, *p_dwv, *p_q, *p_k, *p_v, *p_attn, *p_out0;
    void *p_wqT, *p_wkT, *p_wvT;
    cudaGetSymbolAddress(&p_dwq, g_dwq);
    cudaGetSymbolAddress(&p_dwk, g_dwk);
    cudaGetSymbolAddress(&p_dwv, g_dwv);
    cudaGetSymbolAddress(&p_q,   g_q);
    cudaGetSymbolAddress(&p_k,   g_k);
    cudaGetSymbolAddress(&p_v,   g_v);
    cudaGetSymbolAddress(&p_attn, g_attn);
    cudaGetSymbolAddress(&p_out0, g_out0);
    cudaGetSymbolAddress(&p_wqT, g_wqT);
    cudaGetSymbolAddress(&p_wkT, g_wkT);
    cudaGetSymbolAddress(&p_wvT, g_wvT);

    static int smem_set = 0;
    if (!smem_set) {
        cudaFuncSetAttribute(fused_gate_attn1,
                             cudaFuncAttributeMaxDynamicSharedMemorySize, 8*3*N_*4*2);
        smem_set = 1;
    }

    // weight transposes (tiny) + fused depthwise
    transpose_w<<<dim3(8, 8),  dim3(32,8)>>>(qa_pw_w, (float*)p_wqT, 256);
    transpose_w<<<dim3(32, 8), dim3(32,8)>>>(ka_pw_w, (float*)p_wkT, 1024);
    transpose_w<<<dim3(8, 8),  dim3(32,8)>>>(va_pw_w, (float*)p_wvT, 256);
    dw3_kernel<<<B_*C_, 256>>>(x, qa_dw_w, qa_dw_b, ka_dw_w, ka_dw_b, va_dw_w, va_dw_b);

    // pointwise GEMMs (+bias): Y[oc][n] = sum_c WT[c][oc] * T[c][n]
    gemm128_nn<<<dim3(8, 2, B_), 256>>>((const float*)p_wqT, 0, 0, 256,
                                        (const float*)p_dwq, (size_t)C_*N_, N_,
                                        (float*)p_q, (size_t)C_*N_, N_,
                                        qa_pw_b, 1.f, C_);
    gemm128_nn<<<dim3(8, 8, B_), 256>>>((const float*)p_wkT, 0, 0, 1024,
                                        (const float*)p_dwk, (size_t)C_*N_, N_,
                                        (float*)p_k, (size_t)EXP_*C_*N_, N_,
                                        ka_pw_b, 1.f, C_);
    gemm128_nn<<<dim3(8, 2, B_), 256>>>((const float*)p_wvT, 0, 0, 256,
                                        (const float*)p_dwv, (size_t)C_*N_, N_,
                                        (float*)p_v, (size_t)C_*N_, N_,
                                        va_pw_b, 1.f, C_);

    // qk: attn[z][n][m] = 0.0625 * sum_c q[b][c][n] * k[z][c][m],  z = b*4+e
    gemm128_nn<<<dim3(8, 8, B_*EXP_), 256>>>((const float*)p_q, (size_t)C_*N_, 2, N_,
                                             (const float*)p_k, (size_t)C_*N_, N_,
                                             (float*)p_attn, (size_t)NN_, N_,
                                             nullptr, 0.0625f, C_);

    // FUSED conv0+BN+gate+conv1 -> second output (g_gated never materialized)
    fused_gate_attn1<<<dim3(N_/ROWS_, B_), 256, 8*3*N_*4*2>>>(
        attn0_w, bn_g, bn_b, bn_m, bn_v, attn1_w, out_attn);

    // av: out0[c][n] = sum_m v[c][m] * attnF[n][m]  (both K-minor)
    gemm128_tt<<<dim3(8, 2, B_), 256>>>((const float*)p_v, (size_t)C_*N_, N_,
                                        out_attn, (size_t)NN_, N_,
                                        (float*)p_out0, (size_t)C_*N_, N_, N_);

    // proj 3x3 conv -> first output
    proj_kernel<<<dim3(64, B_), 256>>>(proj_w, out_main);
}

// round 14
// speedup vs baseline: 1.1461x; 1.1461x over previous
#include <cuda_runtime.h>
#include <cstddef>

#define B_   8
#define C_   256
#define N_   1024      // 32*32 spatial flattened
#define EXP_ 4
#define NN_  (N_*N_)
#define ROWS_ 16       // output rows per fused block

// ---------------- scratch (static device arrays; no runtime alloc) -----------
__device__ float g_dwq[B_*C_*N_];
__device__ float g_dwk[B_*C_*N_];
__device__ float g_dwv[B_*C_*N_];
__device__ float g_q  [B_*C_*N_];
__device__ float g_k  [B_*EXP_*C_*N_];
__device__ float g_v  [B_*C_*N_];
__device__ float g_attn [B_*EXP_*NN_];
__device__ float g_out0[B_*C_*N_];
__device__ float g_wqT[C_*C_];
__device__ float g_wkT[C_*EXP_*C_];
__device__ float g_wvT[C_*C_];

__device__ __forceinline__ float tf32r(float x) {
    float y;
    asm("cvt.rna.tf32.f32 %0, %1;" : "=f"(y) : "f"(x));
    return y;
}

// ---------------- weight transpose: in [OC][256] -> out [256][OC] ------------
__global__ void transpose_w(const float* __restrict__ in, float* __restrict__ out, int OC)
{
    __shared__ float t[32][33];
    int oc0 = blockIdx.x * 32, c0 = blockIdx.y * 32;
    int x = threadIdx.x, y = threadIdx.y;
    for (int i = y; i < 32; i += 8) t[i][x] = in[(size_t)(oc0+i)*C_ + c0 + x];
    __syncthreads();
    for (int i = y; i < 32; i += 8) out[(size_t)(c0+i)*OC + oc0 + x] = t[x][i];
}

// ---------------- K1: fused 3-branch depthwise 3x3 + bias --------------------
__global__ void dw3_kernel(const float* __restrict__ x,
                           const float* __restrict__ wq, const float* __restrict__ bq,
                           const float* __restrict__ wk, const float* __restrict__ bk,
                           const float* __restrict__ wv, const float* __restrict__ bv)
{
    __shared__ float plane[N_];
    int bc = blockIdx.x; int b = bc >> 8, c = bc & 255;
    const float* src = x + ((size_t)(b*C_ + c))*N_;
    int tid = threadIdx.x;
    for (int i = tid; i < N_; i += 256) plane[i] = src[i];
    __syncthreads();
    float wwq[9], wwk[9], wwv[9];
    #pragma unroll
    for (int t = 0; t < 9; t++) { wwq[t]=wq[c*9+t]; wwk[t]=wk[c*9+t]; wwv[t]=wv[c*9+t]; }
    float bbq = bq[c], bbk = bk[c], bbv = bv[c];
    for (int i = tid; i < N_; i += 256) {
        int h = i >> 5, w = i & 31;
        float aq = bbq, ak = bbk, av = bbv;
        #pragma unroll
        for (int ky = 0; ky < 3; ky++) {
            int hh = h + ky - 1; if ((unsigned)hh >= 32u) continue;
            #pragma unroll
            for (int kx = 0; kx < 3; kx++) {
                int ww = w + kx - 1; if ((unsigned)ww >= 32u) continue;
                float in = plane[hh*32 + ww];
                aq += wwq[ky*3+kx]*in; ak += wwk[ky*3+kx]*in; av += wwv[ky*3+kx]*in;
            }
        }
        size_t o = ((size_t)(b*C_ + c))*N_ + i;
        g_dwq[o] = aq; g_dwk[o] = ak; g_dwv[o] = av;
    }
}

// ======== TENSOR-CORE tf32 GEMM, both operands K-major ("nn") ================
// C[m][n] = alpha * sum_k A[k][m]*B[k][n] (+ bias[m])
// Block 128x128x16, 8 warps of 64x32, mma.m16n8k8.tf32, fp32 accumulate.
__global__ void __launch_bounds__(256) tgemm_nn(
    const float* __restrict__ A, size_t aBS, int aShift, int lda,
    const float* __restrict__ B, size_t bBS, int ldb,
    float* __restrict__ C, size_t cBS, int ldc,
    const float* __restrict__ bias, float alpha, int K)
{
    __shared__ float As[16][132];
    __shared__ float Bs[16][132];
    int z = blockIdx.z;
    const float* Ag = A + ((size_t)(z >> aShift))*aBS + blockIdx.y*128;
    const float* Bg = B + (size_t)z*bBS + blockIdx.x*128;
    int tid = threadIdx.x;
    int warp = tid >> 5, lane = tid & 31;
    int wm = warp >> 2, wn = warp & 3;          // warp tile: 64m x 32n
    int r  = lane >> 2, kk = lane & 3;

    int lr = tid >> 5, lc = (tid & 31) << 2;

    float4 a0 = *(const float4*)&Ag[(size_t)lr*lda + lc];
    float4 a1 = *(const float4*)&Ag[(size_t)(lr+8)*lda + lc];
    float4 b0 = *(const float4*)&Bg[(size_t)lr*ldb + lc];
    float4 b1 = *(const float4*)&Bg[(size_t)(lr+8)*ldb + lc];

    float acc[4][4][4];
    #pragma unroll
    for (int i = 0; i < 4; i++)
        #pragma unroll
        for (int j = 0; j < 4; j++)
            #pragma unroll
            for (int c = 0; c < 4; c++) acc[i][j][c] = 0.f;

    for (int k0 = 0; k0 < K; k0 += 16) {
        __syncthreads();
        As[lr][lc+0]=tf32r(a0.x); As[lr][lc+1]=tf32r(a0.y); As[lr][lc+2]=tf32r(a0.z); As[lr][lc+3]=tf32r(a0.w);
        As[lr+8][lc+0]=tf32r(a1.x); As[lr+8][lc+1]=tf32r(a1.y); As[lr+8][lc+2]=tf32r(a1.z); As[lr+8][lc+3]=tf32r(a1.w);
        Bs[lr][lc+0]=tf32r(b0.x); Bs[lr][lc+1]=tf32r(b0.y); Bs[lr][lc+2]=tf32r(b0.z); Bs[lr][lc+3]=tf32r(b0.w);
        Bs[lr+8][lc+0]=tf32r(b1.x); Bs[lr+8][lc+1]=tf32r(b1.y); Bs[lr+8][lc+2]=tf32r(b1.z); Bs[lr+8][lc+3]=tf32r(b1.w);
        __syncthreads();
        if (k0 + 16 < K) {
            a0 = *(const float4*)&Ag[(size_t)(k0+16+lr)*lda + lc];
            a1 = *(const float4*)&Ag[(size_t)(k0+24+lr)*lda + lc];
            b0 = *(const float4*)&Bg[(size_t)(k0+16+lr)*ldb + lc];
            b1 = *(const float4*)&Bg[(size_t)(k0+24+lr)*ldb + lc];
        }
        #pragma unroll
        for (int ks = 0; ks < 16; ks += 8) {
            // A fragments for 4 m-tiles (row-major m16xk8 view of As[k][m])
            float af[4][4]; float bf[4][2];
            #pragma unroll
            for (int mt = 0; mt < 4; mt++) {
                int m0 = wm*64 + mt*16;
                af[mt][0] = As[ks+kk  ][m0 + r];
                af[mt][1] = As[ks+kk  ][m0 + r + 8];
                af[mt][2] = As[ks+kk+4][m0 + r];
                af[mt][3] = As[ks+kk+4][m0 + r + 8];
            }
            #pragma unroll
            for (int nt = 0; nt < 4; nt++) {
                int n0 = wn*32 + nt*8;
                bf[nt][0] = Bs[ks+kk  ][n0 + r];
                bf[nt][1] = Bs[ks+kk+4][n0 + r];
            }
            #pragma unroll
            for (int mt = 0; mt < 4; mt++)
                #pragma unroll
                for (int nt = 0; nt < 4; nt++) {
                    asm volatile(
                        "mma.sync.aligned.m16n8k8.row.col.f32.tf32.tf32.f32 "
                        "{%0,%1,%2,%3}, {%4,%5,%6,%7}, {%8,%9}, {%0,%1,%2,%3};"
                        : "+f"(acc[mt][nt][0]), "+f"(acc[mt][nt][1]),
                          "+f"(acc[mt][nt][2]), "+f"(acc[mt][nt][3])
                        : "r"(__float_as_uint(af[mt][0])), "r"(__float_as_uint(af[mt][1])),
                          "r"(__float_as_uint(af[mt][2])), "r"(__float_as_uint(af[mt][3])),
                          "r"(__float_as_uint(bf[nt][0])), "r"(__float_as_uint(bf[nt][1])));
                }
        }
    }
    // epilogue: c0=C[r][2kk], c1=C[r][2kk+1], c2=C[r+8][2kk], c3=C[r+8][2kk+1]
    float* Cg = C + (size_t)z*cBS;
    int mW = blockIdx.y*128 + wm*64, nW = blockIdx.x*128 + wn*32;
    #pragma unroll
    for (int mt = 0; mt < 4; mt++) {
        int m0 = mW + mt*16 + r;
        int m1 = m0 + 8;
        float bi0 = bias ? bias[m0] : 0.f;
        float bi1 = bias ? bias[m1] : 0.f;
        #pragma unroll
        for (int nt = 0; nt < 4; nt++) {
            int n0 = nW + nt*8 + 2*kk;
            float2 o0 = make_float2(acc[mt][nt][0]*alpha + bi0, acc[mt][nt][1]*alpha + bi0);
            float2 o1 = make_float2(acc[mt][nt][2]*alpha + bi1, acc[mt][nt][3]*alpha + bi1);
            *(float2*)&Cg[(size_t)m0*ldc + n0] = o0;
            *(float2*)&Cg[(size_t)m1*ldc + n0] = o1;
        }
    }
}

// ======== 128x128x16 fp32 SGEMM core, both operands K-major ==================
__global__ void __launch_bounds__(256,2) gemm128_nn(
    const float* __restrict__ A, size_t aBS, int aShift, int lda,
    const float* __restrict__ B, size_t bBS, int ldb,
    float* __restrict__ C, size_t cBS, int ldc,
    const float* __restrict__ bias, float alpha, int K)
{
    __shared__ float As[16][132];
    __shared__ float Bs[16][132];
    int z = blockIdx.z;
    const float* Ag = A + ((size_t)(z >> aShift))*aBS + blockIdx.y*128;
    const float* Bg = B + (size_t)z*bBS + blockIdx.x*128;
    int tid = threadIdx.x;
    int tx = tid & 15, ty = tid >> 4;
    int lr = tid >> 5, lc = (tid & 31) << 2;

    float4 a0 = *(const float4*)&Ag[(size_t)lr*lda + lc];
    float4 a1 = *(const float4*)&Ag[(size_t)(lr+8)*lda + lc];
    float4 b0 = *(const float4*)&Bg[(size_t)lr*ldb + lc];
    float4 b1 = *(const float4*)&Bg[(size_t)(lr+8)*ldb + lc];

    float acc[8][8] = {};
    for (int k0 = 0; k0 < K; k0 += 16) {
        __syncthreads();
        *(float4*)&As[lr][lc]   = a0;  *(float4*)&As[lr+8][lc] = a1;
        *(float4*)&Bs[lr][lc]   = b0;  *(float4*)&Bs[lr+8][lc] = b1;
        __syncthreads();
        if (k0 + 16 < K) {
            a0 = *(const float4*)&Ag[(size_t)(k0+16+lr)*lda + lc];
            a1 = *(const float4*)&Ag[(size_t)(k0+24+lr)*lda + lc];
            b0 = *(const float4*)&Bg[(size_t)(k0+16+lr)*ldb + lc];
            b1 = *(const float4*)&Bg[(size_t)(k0+24+lr)*ldb + lc];
        }
        #pragma unroll
        for (int kk = 0; kk < 16; kk++) {
            float4 x0 = *(float4*)&As[kk][ty*8];
            float4 x1 = *(float4*)&As[kk][ty*8+4];
            float4 y0 = *(float4*)&Bs[kk][tx*8];
            float4 y1 = *(float4*)&Bs[kk][tx*8+4];
            float ar[8] = {x0.x,x0.y,x0.z,x0.w,x1.x,x1.y,x1.z,x1.w};
            float br[8] = {y0.x,y0.y,y0.z,y0.w,y1.x,y1.y,y1.z,y1.w};
            #pragma unroll
            for (int i = 0; i < 8; i++)
                #pragma unroll
                for (int j = 0; j < 8; j++) acc[i][j] += ar[i]*br[j];
        }
    }
    float* Cg = C + (size_t)z*cBS;
    int mB = blockIdx.y*128 + ty*8, nB = blockIdx.x*128 + tx*8;
    #pragma unroll
    for (int i = 0; i < 8; i++) {
        int m = mB + i;
        float bi = bias ? bias[m] : 0.f;
        float4 o0 = make_float4(acc[i][0]*alpha+bi, acc[i][1]*alpha+bi,
                                acc[i][2]*alpha+bi, acc[i][3]*alpha+bi);
        float4 o1 = make_float4(acc[i][4]*alpha+bi, acc[i][5]*alpha+bi,
                                acc[i][6]*alpha+bi, acc[i][7]*alpha+bi);
        *(float4*)&Cg[(size_t)m*ldc + nB]     = o0;
        *(float4*)&Cg[(size_t)m*ldc + nB + 4] = o1;
    }
}

// ======== 128x128x16 fp32 core, both operands K-minor ========================
__global__ void __launch_bounds__(256,2) gemm128_tt(
    const float* __restrict__ A, size_t aBS, int lda,
    const float* __restrict__ B, size_t bBS, int ldb,
    float* __restrict__ C, size_t cBS, int ldc, int K)
{
    __shared__ float As[16][132];
    __shared__ float Bs[16][132];
    int z = blockIdx.z;
    const float* Ag = A + (size_t)z*aBS + (size_t)(blockIdx.y*128)*lda;
    const float* Bg = B + (size_t)z*bBS + (size_t)(blockIdx.x*128)*ldb;
    int tid = threadIdx.x;
    int tx = tid & 15, ty = tid >> 4;
    int r0 = tid >> 2, c0 = (tid & 3) << 2;

    float4 a0 = *(const float4*)&Ag[(size_t)r0*lda + c0];
    float4 a1 = *(const float4*)&Ag[(size_t)(r0+64)*lda + c0];
    float4 b0 = *(const float4*)&Bg[(size_t)r0*ldb + c0];
    float4 b1 = *(const float4*)&Bg[(size_t)(r0+64)*ldb + c0];

    float acc[8][8] = {};
    for (int k0 = 0; k0 < K; k0 += 16) {
        __syncthreads();
        As[c0+0][r0]=a0.x; As[c0+1][r0]=a0.y; As[c0+2][r0]=a0.z; As[c0+3][r0]=a0.w;
        As[c0+0][r0+64]=a1.x; As[c0+1][r0+64]=a1.y; As[c0+2][r0+64]=a1.z; As[c0+3][r0+64]=a1.w;
        Bs[c0+0][r0]=b0.x; Bs[c0+1][r0]=b0.y; Bs[c0+2][r0]=b0.z; Bs[c0+3][r0]=b0.w;
        Bs[c0+0][r0+64]=b1.x; Bs[c0+1][r0+64]=b1.y; Bs[c0+2][r0+64]=b1.z; Bs[c0+3][r0+64]=b1.w;
        __syncthreads();
        if (k0 + 16 < K) {
            a0 = *(const float4*)&Ag[(size_t)r0*lda + k0+16 + c0];
            a1 = *(const float4*)&Ag[(size_t)(r0+64)*lda + k0+16 + c0];
            b0 = *(const float4*)&Bg[(size_t)r0*ldb + k0+16 + c0];
            b1 = *(const float4*)&Bg[(size_t)(r0+64)*ldb + k0+16 + c0];
        }
        #pragma unroll
        for (int kk = 0; kk < 16; kk++) {
            float4 x0 = *(float4*)&As[kk][ty*8];
            float4 x1 = *(float4*)&As[kk][ty*8+4];
            float4 y0 = *(float4*)&Bs[kk][tx*8];
            float4 y1 = *(float4*)&Bs[kk][tx*8+4];
            float ar[8] = {x0.x,x0.y,x0.z,x0.w,x1.x,x1.y,x1.z,x1.w};
            float br[8] = {y0.x,y0.y,y0.z,y0.w,y1.x,y1.y,y1.z,y1.w};
            #pragma unroll
            for (int i = 0; i < 8; i++)
                #pragma unroll
                for (int j = 0; j < 8; j++) acc[i][j] += ar[i]*br[j];
        }
    }
    float* Cg = C + (size_t)z*cBS;
    int mB = blockIdx.y*128 + ty*8, nB = blockIdx.x*128 + tx*8;
    #pragma unroll
    for (int i = 0; i < 8; i++) {
        int m = mB + i;
        *(float4*)&Cg[(size_t)m*ldc + nB]     = *(float4*)&acc[i][0];
        *(float4*)&Cg[(size_t)m*ldc + nB + 4] = *(float4*)&acc[i][4];
    }
}

// ======= K45: FUSED conv0(4->4)+BN + self-gated softmax + conv1(4->1) ========
__global__ void __launch_bounds__(256) fused_gate_attn1(
    const float* __restrict__ w0,
    const float* __restrict__ gma, const float* __restrict__ bta,
    const float* __restrict__ mu,  const float* __restrict__ var,
    const float* __restrict__ w1,  float* __restrict__ dst)
{
    extern __shared__ float sm[];
    float* attn_s  = sm;                 // [4][3][N_]
    float* gated_s = sm + 4*3*N_;        // [4][3][N_]
    __shared__ float wsm[144];
    __shared__ float w1sm[36];
    __shared__ float redM[8][4];
    __shared__ float redS[8][4];

    int b = blockIdx.y;
    int r0 = blockIdx.x * ROWS_;
    int tid = threadIdx.x;
    int lane = tid & 31, wid = tid >> 5;

    if (tid < 144) wsm[tid] = w0[tid];
    if (tid < 36)  w1sm[tid] = w1[tid];
    float sc[4], sh[4];
    #pragma unroll
    for (int f = 0; f < 4; f++) {
        float inv = rsqrtf(var[f] + 1e-5f);
        sc[f] = gma[f] * inv; sh[f] = bta[f] - mu[f] * sc[f];
    }

    #define SLOT(r)  (((r) + 3072) % 3)
    #define ATT(e,s,m)   attn_s [(((e)*3)+(s))*N_ + (m)]
    #define GAT(f,s,m)   gated_s[(((f)*3)+(s))*N_ + (m)]

    for (int rr = r0-2; rr <= r0; rr++) {
        int s = SLOT(rr);
        bool ok = (unsigned)rr < (unsigned)N_;
        #pragma unroll
        for (int e = 0; e < 4; e++) {
            float4 v = ok ? *(const float4*)&g_attn[(((size_t)(b*4+e))*N_ + rr)*N_ + tid*4]
                          : make_float4(0.f,0.f,0.f,0.f);
            *(float4*)&ATT(e, s, tid*4) = v;
        }
    }
    __syncthreads();

    for (int g = r0-1; g <= r0+ROWS_; g++) {
        int s1 = SLOT(g);
        if ((unsigned)g < (unsigned)N_) {
            int srow[3] = {SLOT(g-1), s1, SLOT(g+1)};
            float acc[4][4] = {};
            #pragma unroll
            for (int e = 0; e < 4; e++) {
                #pragma unroll
                for (int t = 0; t < 9; t++) {
                    int ky = t/3, kx = t%3;
                    float w0r = wsm[(0*4+e)*9+t], w1r = wsm[(1*4+e)*9+t];
                    float w2r = wsm[(2*4+e)*9+t], w3r = wsm[(3*4+e)*9+t];
                    #pragma unroll
                    for (int j = 0; j < 4; j++) {
                        int m = tid + 256*j + kx - 1;
                        float in = ((unsigned)m < (unsigned)N_) ? ATT(e, srow[ky], m) : 0.f;
                        acc[0][j] += w0r*in; acc[1][j] += w1r*in;
                        acc[2][j] += w2r*in; acc[3][j] += w3r*in;
                    }
                }
            }
            #pragma unroll
            for (int f = 0; f < 4; f++)
                #pragma unroll
                for (int j = 0; j < 4; j++) acc[f][j] = acc[f][j]*sc[f] + sh[f];

            float mx[4];
            #pragma unroll
            for (int f = 0; f < 4; f++)
                mx[f] = fmaxf(fmaxf(acc[f][0], acc[f][1]), fmaxf(acc[f][2], acc[f][3]));
            #pragma unroll
            for (int o = 16; o > 0; o >>= 1)
                #pragma unroll
                for (int f = 0; f < 4; f++)
                    mx[f] = fmaxf(mx[f], __shfl_xor_sync(0xffffffffu, mx[f], o));
            if (lane == 0) { redM[wid][0]=mx[0]; redM[wid][1]=mx[1]; redM[wid][2]=mx[2]; redM[wid][3]=mx[3]; }
            __syncthreads();
            float M[4];
            #pragma unroll
            for (int f = 0; f < 4; f++) {
                float v = redM[0][f];
                #pragma unroll
                for (int w = 1; w < 8; w++) v = fmaxf(v, redM[w][f]);
                M[f] = v;
            }
            float es[4][4], ps[4] = {0.f,0.f,0.f,0.f};
            #pragma unroll
            for (int f = 0; f < 4; f++)
                #pragma unroll
                for (int j = 0; j < 4; j++) { es[f][j] = __expf(acc[f][j] - M[f]); ps[f] += es[f][j]; }
            #pragma unroll
            for (int o = 16; o > 0; o >>= 1)
                #pragma unroll
                for (int f = 0; f < 4; f++)
                    ps[f] += __shfl_xor_sync(0xffffffffu, ps[f], o);
            if (lane == 0) { redS[wid][0]=ps[0]; redS[wid][1]=ps[1]; redS[wid][2]=ps[2]; redS[wid][3]=ps[3]; }
            __syncthreads();
            float invS[4];
            #pragma unroll
            for (int f = 0; f < 4; f++) {
                float v = 0.f;
                #pragma unroll
                for (int w = 0; w < 8; w++) v += redS[w][f];
                invS[f] = 1.f / v;
            }
            #pragma unroll
            for (int f = 0; f < 4; f++)
                #pragma unroll
                for (int j = 0; j < 4; j++)
                    GAT(f, s1, tid + 256*j) = acc[f][j] * es[f][j] * invS[f];
        } else {
            #pragma unroll
            for (int f = 0; f < 4; f++)
                #pragma unroll
                for (int j = 0; j < 4; j++) GAT(f, s1, tid + 256*j) = 0.f;
        }
        __syncthreads();

        if (g >= r0+1) {
            int n = g-1;
            int trow[3] = {SLOT(n-1), SLOT(n), SLOT(n+1)};
            float acc2[4] = {};
            #pragma unroll
            for (int e = 0; e < 4; e++)
                #pragma unroll
                for (int t = 0; t < 9; t++) {
                    int ky = t/3, kx = t%3;
                    float wv = w1sm[e*9 + t];
                    #pragma unroll
                    for (int j = 0; j < 4; j++) {
                        int m = tid + 256*j + kx - 1;
                        float in = ((unsigned)m < (unsigned)N_) ? GAT(e, trow[ky], m) : 0.f;
                        acc2[j] += wv*in;
                    }
                }
            #pragma unroll
            for (int j = 0; j < 4; j++)
                dst[((size_t)b*N_ + n)*N_ + tid + 256*j] = acc2[j];
        }

        if (g < r0+ROWS_) {
            int rr = g+2; int s = SLOT(rr);
            bool ok = (unsigned)rr < (unsigned)N_;
            #pragma unroll
            for (int e = 0; e < 4; e++) {
                float4 v = ok ? *(const float4*)&g_attn[(((size_t)(b*4+e))*N_ + rr)*N_ + tid*4]
                              : make_float4(0.f,0.f,0.f,0.f);
                *(float4*)&ATT(e, s, tid*4) = v;
            }
        }
        __syncthreads();
    }
    #undef SLOT
    #undef ATT
    #undef GAT
}

// ---------------- K7: proj 3x3 conv (256->256, no bias) -> first output ------
__global__ void proj_kernel(const float* __restrict__ pw, float* __restrict__ dst)
{
    __shared__ float inT[8][34*34];
    __shared__ float wT[4][8][9];
    int ocg = blockIdx.x;
    int b   = blockIdx.y;
    int tid = threadIdx.x;
    int base34[4];
    #pragma unroll
    for (int i = 0; i < 4; i++) {
        int sp = tid + 256*i; int h = sp >> 5, w = sp & 31;
        base34[i] = h*34 + w;
    }
    float acc[4][4] = {};
    for (int cc = 0; cc < 32; cc++) {
        __syncthreads();
        for (int idx = tid; idx < 8*1156; idx += 256) {
            int ic = idx / 1156, rem = idx % 1156;
            int hh = rem / 34 - 1, ww = rem % 34 - 1;
            float v = 0.f;
            if ((unsigned)hh < 32u && (unsigned)ww < 32u)
                v = g_out0[((size_t)b*C_ + cc*8 + ic)*N_ + hh*32 + ww];
            inT[ic][rem] = v;
        }
        for (int idx = tid; idx < 288; idx += 256) {
            int oc = idx / 72, r2 = idx % 72, ic = r2 / 9, t = r2 % 9;
            wT[oc][ic][t] = pw[((size_t)(ocg*4 + oc)*C_ + cc*8 + ic)*9 + t];
        }
        __syncthreads();
        #pragma unroll
        for (int ic = 0; ic < 8; ic++) {
            #pragma unroll
            for (int t = 0; t < 9; t++) {
                int off = (t/3)*34 + (t%3);
                float w0 = wT[0][ic][t], w1 = wT[1][ic][t];
                float w2 = wT[2][ic][t], w3 = wT[3][ic][t];
                #pragma unroll
                for (int i = 0; i < 4; i++) {
                    float in = inT[ic][base34[i] + off];
                    acc[0][i] += w0*in; acc[1][i] += w1*in;
                    acc[2][i] += w2*in; acc[3][i] += w3*in;
                }
            }
        }
    }
    #pragma unroll
    for (int oc = 0; oc < 4; oc++)
        #pragma unroll
        for (int i = 0; i < 4; i++)
            dst[((size_t)b*C_ + ocg*4 + oc)*N_ + tid + 256*i] = acc[oc][i];
}

// ---------------------------------------------------------------------------
extern "C" void kernel_launch(void* const* d_in, const int* in_sizes, int n_in,
                              void* d_out, int out_size)
{
    const float* x       = (const float*)d_in[0];
    const float* qa_dw_w = (const float*)d_in[1];
    const float* qa_dw_b = (const float*)d_in[2];
    const float* qa_pw_w = (const float*)d_in[3];
    const float* qa_pw_b = (const float*)d_in[4];
    const float* ka_dw_w = (const float*)d_in[5];
    const float* ka_dw_b = (const float*)d_in[6];
    const float* ka_pw_w = (const float*)d_in[7];
    const float* ka_pw_b = (const float*)d_in[8];
    const float* va_dw_w = (const float*)d_in[9];
    const float* va_dw_b = (const float*)d_in[10];
    const float* va_pw_w = (const float*)d_in[11];
    const float* va_pw_b = (const float*)d_in[12];
    const float* attn0_w = (const float*)d_in[13];
    const float* bn_g    = (const float*)d_in[14];
    const float* bn_b    = (const float*)d_in[15];
    const float* bn_m    = (const float*)d_in[16];
    const float* bn_v    = (const float*)d_in[17];
    const float* attn1_w = (const float*)d_in[18];
    const float* proj_w  = (const float*)d_in[19];

    float* out_main = (float*)d_out;                 // [8,256,32,32]
    float* out_attn = out_main + (size_t)B_*C_*N_;   // [8,1,1024,1024]

    void *p_dwq, *p_dwk, *p_dwv, *p_q, *p_k, *p_v, *p_attn, *p_out0;
    void *p_wqT, *p_wkT, *p_wvT;
    cudaGetSymbolAddress(&p_dwq, g_dwq);
    cudaGetSymbolAddress(&p_dwk, g_dwk);
    cudaGetSymbolAddress(&p_dwv, g_dwv);
    cudaGetSymbolAddress(&p_q,   g_q);
    cudaGetSymbolAddress(&p_k,   g_k);
    cudaGetSymbolAddress(&p_v,   g_v);
    cudaGetSymbolAddress(&p_attn, g_attn);
    cudaGetSymbolAddress(&p_out0, g_out0);
    cudaGetSymbolAddress(&p_wqT, g_wqT);
    cudaGetSymbolAddress(&p_wkT, g_wkT);
    cudaGetSymbolAddress(&p_wvT, g_wvT);

    static int smem_set = 0;
    if (!smem_set) {
        cudaFuncSetAttribute(fused_gate_attn1,
                             cudaFuncAttributeMaxDynamicSharedMemorySize, 8*3*N_*4*2);
        smem_set = 1;
    }

    transpose_w<<<dim3(8, 8),  dim3(32,8)>>>(qa_pw_w, (float*)p_wqT, 256);
    transpose_w<<<dim3(32, 8), dim3(32,8)>>>(ka_pw_w, (float*)p_wkT, 1024);
    transpose_w<<<dim3(8, 8),  dim3(32,8)>>>(va_pw_w, (float*)p_wvT, 256);
    dw3_kernel<<<B_*C_, 256>>>(x, qa_dw_w, qa_dw_b, ka_dw_w, ka_dw_b, va_dw_w, va_dw_b);

    // pointwise GEMMs: q/v on fp32 core, k (4x larger) on tensor core
    gemm128_nn<<<dim3(8, 2, B_), 256>>>((const float*)p_wqT, 0, 0, 256,
                                        (const float*)p_dwq, (size_t)C_*N_, N_,
                                        (float*)p_q, (size_t)C_*N_, N_,
                                        qa_pw_b, 1.f, C_);
    tgemm_nn<<<dim3(8, 8, B_), 256>>>((const float*)p_wkT, 0, 0, 1024,
                                      (const float*)p_dwk, (size_t)C_*N_, N_,
                                      (float*)p_k, (size_t)EXP_*C_*N_, N_,
                                      ka_pw_b, 1.f, C_);
    gemm128_nn<<<dim3(8, 2, B_), 256>>>((const float*)p_wvT, 0, 0, 256,
                                        (const float*)p_dwv, (size_t)C_*N_, N_,
                                        (float*)p_v, (size_t)C_*N_, N_,
                                        va_pw_b, 1.f, C_);

    // qk on tensor core: attn[z][n][m] = 0.0625 * sum_c q[b][c][n]*k[z][c][m]
    tgemm_nn<<<dim3(8, 8, B_*EXP_), 256>>>((const float*)p_q, (size_t)C_*N_, 2, N_,
                                           (const float*)p_k, (size_t)C_*N_, N_,
                                           (float*)p_attn, (size_t)NN_, N_,
                                           nullptr, 0.0625f, C_);

    // FUSED conv0+BN+gate+conv1 -> second output
    fused_gate_attn1<<<dim3(N_/ROWS_, B_), 256, 8*3*N_*4*2>>>(
        attn0_w, bn_g, bn_b, bn_m, bn_v, attn1_w, out_attn);

    // av: out0[c][n] = sum_m v[c][m] * attnF[n][m]  (fp32)
    gemm128_tt<<<dim3(8, 2, B_), 256>>>((const float*)p_v, (size_t)C_*N_, N_,
                                        out_attn, (size_t)NN_, N_,
                                        (float*)p_out0, (size_t)C_*N_, N_, N_);

    // proj 3x3 conv -> first output
    proj_kernel<<<dim3(64, B_), 256>>>(proj_w, out_main);
}

// round 15
// speedup vs baseline: 1.1867x; 1.0354x over previous
#include <cuda_runtime.h>
#include <cstddef>

#define B_   8
#define C_   256
#define N_   1024      // 32*32 spatial flattened
#define EXP_ 4
#define NN_  (N_*N_)
#define ROWS_ 16       // output rows per fused block

// ---------------- scratch (static device arrays; no runtime alloc) -----------
__device__ float g_dwq[B_*C_*N_];
__device__ float g_dwk[B_*C_*N_];
__device__ float g_dwv[B_*C_*N_];
__device__ float g_q  [B_*C_*N_];
__device__ float g_k  [B_*EXP_*C_*N_];
__device__ float g_v  [B_*C_*N_];
__device__ float g_attn [B_*EXP_*NN_];
__device__ float g_out0[B_*C_*N_];
__device__ float g_wqT[C_*C_];
__device__ float g_wkT[C_*EXP_*C_];
__device__ float g_wvT[C_*C_];

__device__ __forceinline__ float tf32r(float x) {
    float y;
    asm("cvt.rna.tf32.f32 %0, %1;" : "=f"(y) : "f"(x));
    return y;
}

#define MMA_TF32(acc, af, bf)                                                  \
    asm volatile(                                                              \
        "mma.sync.aligned.m16n8k8.row.col.f32.tf32.tf32.f32 "                  \
        "{%0,%1,%2,%3}, {%4,%5,%6,%7}, {%8,%9}, {%0,%1,%2,%3};"                \
        : "+f"((acc)[0]), "+f"((acc)[1]), "+f"((acc)[2]), "+f"((acc)[3])       \
        : "r"(__float_as_uint((af)[0])), "r"(__float_as_uint((af)[1])),        \
          "r"(__float_as_uint((af)[2])), "r"(__float_as_uint((af)[3])),        \
          "r"(__float_as_uint((bf)[0])), "r"(__float_as_uint((bf)[1])))

// ---------------- weight transpose: in [OC][256] -> out [256][OC] ------------
__global__ void transpose_w(const float* __restrict__ in, float* __restrict__ out, int OC)
{
    __shared__ float t[32][33];
    int oc0 = blockIdx.x * 32, c0 = blockIdx.y * 32;
    int x = threadIdx.x, y = threadIdx.y;
    for (int i = y; i < 32; i += 8) t[i][x] = in[(size_t)(oc0+i)*C_ + c0 + x];
    __syncthreads();
    for (int i = y; i < 32; i += 8) out[(size_t)(c0+i)*OC + oc0 + x] = t[x][i];
}

// ---------------- K1: fused 3-branch depthwise 3x3 + bias --------------------
__global__ void dw3_kernel(const float* __restrict__ x,
                           const float* __restrict__ wq, const float* __restrict__ bq,
                           const float* __restrict__ wk, const float* __restrict__ bk,
                           const float* __restrict__ wv, const float* __restrict__ bv)
{
    __shared__ float plane[N_];
    int bc = blockIdx.x; int b = bc >> 8, c = bc & 255;
    const float* src = x + ((size_t)(b*C_ + c))*N_;
    int tid = threadIdx.x;
    for (int i = tid; i < N_; i += 256) plane[i] = src[i];
    __syncthreads();
    float wwq[9], wwk[9], wwv[9];
    #pragma unroll
    for (int t = 0; t < 9; t++) { wwq[t]=wq[c*9+t]; wwk[t]=wk[c*9+t]; wwv[t]=wv[c*9+t]; }
    float bbq = bq[c], bbk = bk[c], bbv = bv[c];
    for (int i = tid; i < N_; i += 256) {
        int h = i >> 5, w = i & 31;
        float aq = bbq, ak = bbk, av = bbv;
        #pragma unroll
        for (int ky = 0; ky < 3; ky++) {
            int hh = h + ky - 1; if ((unsigned)hh >= 32u) continue;
            #pragma unroll
            for (int kx = 0; kx < 3; kx++) {
                int ww = w + kx - 1; if ((unsigned)ww >= 32u) continue;
                float in = plane[hh*32 + ww];
                aq += wwq[ky*3+kx]*in; ak += wwk[ky*3+kx]*in; av += wwv[ky*3+kx]*in;
            }
        }
        size_t o = ((size_t)(b*C_ + c))*N_ + i;
        g_dwq[o] = aq; g_dwk[o] = ak; g_dwv[o] = av;
    }
}

// ======== TENSOR-CORE tf32 GEMM, both operands K-major ("nn") ================
// C[m][n] = alpha * sum_k A[k][m]*B[k][n] (+ bias[m])
// Block 128x128x16, 8 warps of 64x32, mma.m16n8k8.tf32, fp32 accumulate.
__global__ void __launch_bounds__(256) tgemm_nn(
    const float* __restrict__ A, size_t aBS, int aShift, int lda,
    const float* __restrict__ B, size_t bBS, int ldb,
    float* __restrict__ C, size_t cBS, int ldc,
    const float* __restrict__ bias, float alpha, int K)
{
    __shared__ float As[16][132];
    __shared__ float Bs[16][132];
    int z = blockIdx.z;
    const float* Ag = A + ((size_t)(z >> aShift))*aBS + blockIdx.y*128;
    const float* Bg = B + (size_t)z*bBS + blockIdx.x*128;
    int tid = threadIdx.x;
    int warp = tid >> 5, lane = tid & 31;
    int wm = warp >> 2, wn = warp & 3;          // warp tile: 64m x 32n
    int r  = lane >> 2, kk = lane & 3;

    int lr = tid >> 5, lc = (tid & 31) << 2;

    float4 a0 = *(const float4*)&Ag[(size_t)lr*lda + lc];
    float4 a1 = *(const float4*)&Ag[(size_t)(lr+8)*lda + lc];
    float4 b0 = *(const float4*)&Bg[(size_t)lr*ldb + lc];
    float4 b1 = *(const float4*)&Bg[(size_t)(lr+8)*ldb + lc];

    float acc[4][4][4];
    #pragma unroll
    for (int i = 0; i < 4; i++)
        #pragma unroll
        for (int j = 0; j < 4; j++)
            #pragma unroll
            for (int c = 0; c < 4; c++) acc[i][j][c] = 0.f;

    for (int k0 = 0; k0 < K; k0 += 16) {
        __syncthreads();
        As[lr][lc+0]=tf32r(a0.x); As[lr][lc+1]=tf32r(a0.y); As[lr][lc+2]=tf32r(a0.z); As[lr][lc+3]=tf32r(a0.w);
        As[lr+8][lc+0]=tf32r(a1.x); As[lr+8][lc+1]=tf32r(a1.y); As[lr+8][lc+2]=tf32r(a1.z); As[lr+8][lc+3]=tf32r(a1.w);
        Bs[lr][lc+0]=tf32r(b0.x); Bs[lr][lc+1]=tf32r(b0.y); Bs[lr][lc+2]=tf32r(b0.z); Bs[lr][lc+3]=tf32r(b0.w);
        Bs[lr+8][lc+0]=tf32r(b1.x); Bs[lr+8][lc+1]=tf32r(b1.y); Bs[lr+8][lc+2]=tf32r(b1.z); Bs[lr+8][lc+3]=tf32r(b1.w);
        __syncthreads();
        if (k0 + 16 < K) {
            a0 = *(const float4*)&Ag[(size_t)(k0+16+lr)*lda + lc];
            a1 = *(const float4*)&Ag[(size_t)(k0+24+lr)*lda + lc];
            b0 = *(const float4*)&Bg[(size_t)(k0+16+lr)*ldb + lc];
            b1 = *(const float4*)&Bg[(size_t)(k0+24+lr)*ldb + lc];
        }
        #pragma unroll
        for (int ks = 0; ks < 16; ks += 8) {
            float af[4][4]; float bf[4][2];
            #pragma unroll
            for (int mt = 0; mt < 4; mt++) {
                int m0 = wm*64 + mt*16;
                af[mt][0] = As[ks+kk  ][m0 + r];
                af[mt][1] = As[ks+kk  ][m0 + r + 8];
                af[mt][2] = As[ks+kk+4][m0 + r];
                af[mt][3] = As[ks+kk+4][m0 + r + 8];
            }
            #pragma unroll
            for (int nt = 0; nt < 4; nt++) {
                int n0 = wn*32 + nt*8;
                bf[nt][0] = Bs[ks+kk  ][n0 + r];
                bf[nt][1] = Bs[ks+kk+4][n0 + r];
            }
            #pragma unroll
            for (int mt = 0; mt < 4; mt++)
                #pragma unroll
                for (int nt = 0; nt < 4; nt++)
                    MMA_TF32(acc[mt][nt], af[mt], bf[nt]);
        }
    }
    float* Cg = C + (size_t)z*cBS;
    int mW = blockIdx.y*128 + wm*64, nW = blockIdx.x*128 + wn*32;
    #pragma unroll
    for (int mt = 0; mt < 4; mt++) {
        int m0 = mW + mt*16 + r;
        int m1 = m0 + 8;
        float bi0 = bias ? bias[m0] : 0.f;
        float bi1 = bias ? bias[m1] : 0.f;
        #pragma unroll
        for (int nt = 0; nt < 4; nt++) {
            int n0 = nW + nt*8 + 2*kk;
            float2 o0 = make_float2(acc[mt][nt][0]*alpha + bi0, acc[mt][nt][1]*alpha + bi0);
            float2 o1 = make_float2(acc[mt][nt][2]*alpha + bi1, acc[mt][nt][3]*alpha + bi1);
            *(float2*)&Cg[(size_t)m0*ldc + n0] = o0;
            *(float2*)&Cg[(size_t)m1*ldc + n0] = o1;
        }
    }
}

// ======== TENSOR-CORE tf32 GEMM, both operands K-minor ("tt") ================
// C[m][n] = sum_k A[m][k]*B[n][k]; transpose happens on the smem store.
__global__ void __launch_bounds__(256) tgemm_tt(
    const float* __restrict__ A, size_t aBS, int lda,
    const float* __restrict__ B, size_t bBS, int ldb,
    float* __restrict__ C, size_t cBS, int ldc, int K)
{
    __shared__ float As[16][132];
    __shared__ float Bs[16][132];
    int z = blockIdx.z;
    const float* Ag = A + (size_t)z*aBS + (size_t)(blockIdx.y*128)*lda;
    const float* Bg = B + (size_t)z*bBS + (size_t)(blockIdx.x*128)*ldb;
    int tid = threadIdx.x;
    int warp = tid >> 5, lane = tid & 31;
    int wm = warp >> 2, wn = warp & 3;
    int r  = lane >> 2, kk = lane & 3;
    int r0 = tid >> 2, c0 = (tid & 3) << 2;

    float4 a0 = *(const float4*)&Ag[(size_t)r0*lda + c0];
    float4 a1 = *(const float4*)&Ag[(size_t)(r0+64)*lda + c0];
    float4 b0 = *(const float4*)&Bg[(size_t)r0*ldb + c0];
    float4 b1 = *(const float4*)&Bg[(size_t)(r0+64)*ldb + c0];

    float acc[4][4][4];
    #pragma unroll
    for (int i = 0; i < 4; i++)
        #pragma unroll
        for (int j = 0; j < 4; j++)
            #pragma unroll
            for (int c = 0; c < 4; c++) acc[i][j][c] = 0.f;

    for (int k0 = 0; k0 < K; k0 += 16) {
        __syncthreads();
        As[c0+0][r0]=tf32r(a0.x); As[c0+1][r0]=tf32r(a0.y); As[c0+2][r0]=tf32r(a0.z); As[c0+3][r0]=tf32r(a0.w);
        As[c0+0][r0+64]=tf32r(a1.x); As[c0+1][r0+64]=tf32r(a1.y); As[c0+2][r0+64]=tf32r(a1.z); As[c0+3][r0+64]=tf32r(a1.w);
        Bs[c0+0][r0]=tf32r(b0.x); Bs[c0+1][r0]=tf32r(b0.y); Bs[c0+2][r0]=tf32r(b0.z); Bs[c0+3][r0]=tf32r(b0.w);
        Bs[c0+0][r0+64]=tf32r(b1.x); Bs[c0+1][r0+64]=tf32r(b1.y); Bs[c0+2][r0+64]=tf32r(b1.z); Bs[c0+3][r0+64]=tf32r(b1.w);
        __syncthreads();
        if (k0 + 16 < K) {
            a0 = *(const float4*)&Ag[(size_t)r0*lda + k0+16 + c0];
            a1 = *(const float4*)&Ag[(size_t)(r0+64)*lda + k0+16 + c0];
            b0 = *(const float4*)&Bg[(size_t)r0*ldb + k0+16 + c0];
            b1 = *(const float4*)&Bg[(size_t)(r0+64)*ldb + k0+16 + c0];
        }
        #pragma unroll
        for (int ks = 0; ks < 16; ks += 8) {
            float af[4][4]; float bf[4][2];
            #pragma unroll
            for (int mt = 0; mt < 4; mt++) {
                int m0 = wm*64 + mt*16;
                af[mt][0] = As[ks+kk  ][m0 + r];
                af[mt][1] = As[ks+kk  ][m0 + r + 8];
                af[mt][2] = As[ks+kk+4][m0 + r];
                af[mt][3] = As[ks+kk+4][m0 + r + 8];
            }
            #pragma unroll
            for (int nt = 0; nt < 4; nt++) {
                int n0 = wn*32 + nt*8;
                bf[nt][0] = Bs[ks+kk  ][n0 + r];
                bf[nt][1] = Bs[ks+kk+4][n0 + r];
            }
            #pragma unroll
            for (int mt = 0; mt < 4; mt++)
                #pragma unroll
                for (int nt = 0; nt < 4; nt++)
                    MMA_TF32(acc[mt][nt], af[mt], bf[nt]);
        }
    }
    float* Cg = C + (size_t)z*cBS;
    int mW = blockIdx.y*128 + wm*64, nW = blockIdx.x*128 + wn*32;
    #pragma unroll
    for (int mt = 0; mt < 4; mt++) {
        int m0 = mW + mt*16 + r;
        int m1 = m0 + 8;
        #pragma unroll
        for (int nt = 0; nt < 4; nt++) {
            int n0 = nW + nt*8 + 2*kk;
            *(float2*)&Cg[(size_t)m0*ldc + n0] = make_float2(acc[mt][nt][0], acc[mt][nt][1]);
            *(float2*)&Cg[(size_t)m1*ldc + n0] = make_float2(acc[mt][nt][2], acc[mt][nt][3]);
        }
    }
}

// ======= K45: FUSED conv0(4->4)+BN + self-gated softmax + conv1(4->1) ========
__global__ void __launch_bounds__(256) fused_gate_attn1(
    const float* __restrict__ w0,
    const float* __restrict__ gma, const float* __restrict__ bta,
    const float* __restrict__ mu,  const float* __restrict__ var,
    const float* __restrict__ w1,  float* __restrict__ dst)
{
    extern __shared__ float sm[];
    float* attn_s  = sm;                 // [4][3][N_]
    float* gated_s = sm + 4*3*N_;        // [4][3][N_]
    __shared__ float wsm[144];
    __shared__ float w1sm[36];
    __shared__ float redM[8][4];
    __shared__ float redS[8][4];

    int b = blockIdx.y;
    int r0 = blockIdx.x * ROWS_;
    int tid = threadIdx.x;
    int lane = tid & 31, wid = tid >> 5;

    if (tid < 144) wsm[tid] = w0[tid];
    if (tid < 36)  w1sm[tid] = w1[tid];
    float sc[4], sh[4];
    #pragma unroll
    for (int f = 0; f < 4; f++) {
        float inv = rsqrtf(var[f] + 1e-5f);
        sc[f] = gma[f] * inv; sh[f] = bta[f] - mu[f] * sc[f];
    }

    #define SLOT(r)  (((r) + 3072) % 3)
    #define ATT(e,s,m)   attn_s [(((e)*3)+(s))*N_ + (m)]
    #define GAT(f,s,m)   gated_s[(((f)*3)+(s))*N_ + (m)]

    for (int rr = r0-2; rr <= r0; rr++) {
        int s = SLOT(rr);
        bool ok = (unsigned)rr < (unsigned)N_;
        #pragma unroll
        for (int e = 0; e < 4; e++) {
            float4 v = ok ? *(const float4*)&g_attn[(((size_t)(b*4+e))*N_ + rr)*N_ + tid*4]
                          : make_float4(0.f,0.f,0.f,0.f);
            *(float4*)&ATT(e, s, tid*4) = v;
        }
    }
    __syncthreads();

    for (int g = r0-1; g <= r0+ROWS_; g++) {
        int s1 = SLOT(g);
        if ((unsigned)g < (unsigned)N_) {
            int srow[3] = {SLOT(g-1), s1, SLOT(g+1)};
            float acc[4][4] = {};
            #pragma unroll
            for (int e = 0; e < 4; e++) {
                #pragma unroll
                for (int t = 0; t < 9; t++) {
                    int ky = t/3, kx = t%3;
                    float w0r = wsm[(0*4+e)*9+t], w1r = wsm[(1*4+e)*9+t];
                    float w2r = wsm[(2*4+e)*9+t], w3r = wsm[(3*4+e)*9+t];
                    #pragma unroll
                    for (int j = 0; j < 4; j++) {
                        int m = tid + 256*j + kx - 1;
                        float in = ((unsigned)m < (unsigned)N_) ? ATT(e, srow[ky], m) : 0.f;
                        acc[0][j] += w0r*in; acc[1][j] += w1r*in;
                        acc[2][j] += w2r*in; acc[3][j] += w3r*in;
                    }
                }
            }
            #pragma unroll
            for (int f = 0; f < 4; f++)
                #pragma unroll
                for (int j = 0; j < 4; j++) acc[f][j] = acc[f][j]*sc[f] + sh[f];

            float mx[4];
            #pragma unroll
            for (int f = 0; f < 4; f++)
                mx[f] = fmaxf(fmaxf(acc[f][0], acc[f][1]), fmaxf(acc[f][2], acc[f][3]));
            #pragma unroll
            for (int o = 16; o > 0; o >>= 1)
                #pragma unroll
                for (int f = 0; f < 4; f++)
                    mx[f] = fmaxf(mx[f], __shfl_xor_sync(0xffffffffu, mx[f], o));
            if (lane == 0) { redM[wid][0]=mx[0]; redM[wid][1]=mx[1]; redM[wid][2]=mx[2]; redM[wid][3]=mx[3]; }
            __syncthreads();
            float M[4];
            #pragma unroll
            for (int f = 0; f < 4; f++) {
                float v = redM[0][f];
                #pragma unroll
                for (int w = 1; w < 8; w++) v = fmaxf(v, redM[w][f]);
                M[f] = v;
            }
            float es[4][4], ps[4] = {0.f,0.f,0.f,0.f};
            #pragma unroll
            for (int f = 0; f < 4; f++)
                #pragma unroll
                for (int j = 0; j < 4; j++) { es[f][j] = __expf(acc[f][j] - M[f]); ps[f] += es[f][j]; }
            #pragma unroll
            for (int o = 16; o > 0; o >>= 1)
                #pragma unroll
                for (int f = 0; f < 4; f++)
                    ps[f] += __shfl_xor_sync(0xffffffffu, ps[f], o);
            if (lane == 0) { redS[wid][0]=ps[0]; redS[wid][1]=ps[1]; redS[wid][2]=ps[2]; redS[wid][3]=ps[3]; }
            __syncthreads();
            float invS[4];
            #pragma unroll
            for (int f = 0; f < 4; f++) {
                float v = 0.f;
                #pragma unroll
                for (int w = 0; w < 8; w++) v += redS[w][f];
                invS[f] = 1.f / v;
            }
            #pragma unroll
            for (int f = 0; f < 4; f++)
                #pragma unroll
                for (int j = 0; j < 4; j++)
                    GAT(f, s1, tid + 256*j) = acc[f][j] * es[f][j] * invS[f];
        } else {
            #pragma unroll
            for (int f = 0; f < 4; f++)
                #pragma unroll
                for (int j = 0; j < 4; j++) GAT(f, s1, tid + 256*j) = 0.f;
        }
        __syncthreads();

        if (g >= r0+1) {
            int n = g-1;
            int trow[3] = {SLOT(n-1), SLOT(n), SLOT(n+1)};
            float acc2[4] = {};
            #pragma unroll
            for (int e = 0; e < 4; e++)
                #pragma unroll
                for (int t = 0; t < 9; t++) {
                    int ky = t/3, kx = t%3;
                    float wv = w1sm[e*9 + t];
                    #pragma unroll
                    for (int j = 0; j < 4; j++) {
                        int m = tid + 256*j + kx - 1;
                        float in = ((unsigned)m < (unsigned)N_) ? GAT(e, trow[ky], m) : 0.f;
                        acc2[j] += wv*in;
                    }
                }
            #pragma unroll
            for (int j = 0; j < 4; j++)
                dst[((size_t)b*N_ + n)*N_ + tid + 256*j] = acc2[j];
        }

        if (g < r0+ROWS_) {
            int rr = g+2; int s = SLOT(rr);
            bool ok = (unsigned)rr < (unsigned)N_;
            #pragma unroll
            for (int e = 0; e < 4; e++) {
                float4 v = ok ? *(const float4*)&g_attn[(((size_t)(b*4+e))*N_ + rr)*N_ + tid*4]
                              : make_float4(0.f,0.f,0.f,0.f);
                *(float4*)&ATT(e, s, tid*4) = v;
            }
        }
        __syncthreads();
    }
    #undef SLOT
    #undef ATT
    #undef GAT
}

// ---------------- K7: proj 3x3 conv (256->256, no bias) -> first output ------
__global__ void proj_kernel(const float* __restrict__ pw, float* __restrict__ dst)
{
    __shared__ float inT[8][34*34];
    __shared__ float wT[4][8][9];
    int ocg = blockIdx.x;
    int b   = blockIdx.y;
    int tid = threadIdx.x;
    int base34[4];
    #pragma unroll
    for (int i = 0; i < 4; i++) {
        int sp = tid + 256*i; int h = sp >> 5, w = sp & 31;
        base34[i] = h*34 + w;
    }
    float acc[4][4] = {};
    for (int cc = 0; cc < 32; cc++) {
        __syncthreads();
        for (int idx = tid; idx < 8*1156; idx += 256) {
            int ic = idx / 1156, rem = idx % 1156;
            int hh = rem / 34 - 1, ww = rem % 34 - 1;
            float v = 0.f;
            if ((unsigned)hh < 32u && (unsigned)ww < 32u)
                v = g_out0[((size_t)b*C_ + cc*8 + ic)*N_ + hh*32 + ww];
            inT[ic][rem] = v;
        }
        for (int idx = tid; idx < 288; idx += 256) {
            int oc = idx / 72, r2 = idx % 72, ic = r2 / 9, t = r2 % 9;
            wT[oc][ic][t] = pw[((size_t)(ocg*4 + oc)*C_ + cc*8 + ic)*9 + t];
        }
        __syncthreads();
        #pragma unroll
        for (int ic = 0; ic < 8; ic++) {
            #pragma unroll
            for (int t = 0; t < 9; t++) {
                int off = (t/3)*34 + (t%3);
                float w0 = wT[0][ic][t], w1 = wT[1][ic][t];
                float w2 = wT[2][ic][t], w3 = wT[3][ic][t];
                #pragma unroll
                for (int i = 0; i < 4; i++) {
                    float in = inT[ic][base34[i] + off];
                    acc[0][i] += w0*in; acc[1][i] += w1*in;
                    acc[2][i] += w2*in; acc[3][i] += w3*in;
                }
            }
        }
    }
    #pragma unroll
    for (int oc = 0; oc < 4; oc++)
        #pragma unroll
        for (int i = 0; i < 4; i++)
            dst[((size_t)b*C_ + ocg*4 + oc)*N_ + tid + 256*i] = acc[oc][i];
}

// ---------------------------------------------------------------------------
extern "C" void kernel_launch(void* const* d_in, const int* in_sizes, int n_in,
                              void* d_out, int out_size)
{
    const float* x       = (const float*)d_in[0];
    const float* qa_dw_w = (const float*)d_in[1];
    const float* qa_dw_b = (const float*)d_in[2];
    const float* qa_pw_w = (const float*)d_in[3];
    const float* qa_pw_b = (const float*)d_in[4];
    const float* ka_dw_w = (const float*)d_in[5];
    const float* ka_dw_b = (const float*)d_in[6];
    const float* ka_pw_w = (const float*)d_in[7];
    const float* ka_pw_b = (const float*)d_in[8];
    const float* va_dw_w = (const float*)d_in[9];
    const float* va_dw_b = (const float*)d_in[10];
    const float* va_pw_w = (const float*)d_in[11];
    const float* va_pw_b = (const float*)d_in[12];
    const float* attn0_w = (const float*)d_in[13];
    const float* bn_g    = (const float*)d_in[14];
    const float* bn_b    = (const float*)d_in[15];
    const float* bn_m    = (const float*)d_in[16];
    const float* bn_v    = (const float*)d_in[17];
    const float* attn1_w = (const float*)d_in[18];
    const float* proj_w  = (const float*)d_in[19];

    float* out_main = (float*)d_out;                 // [8,256,32,32]
    float* out_attn = out_main + (size_t)B_*C_*N_;   // [8,1,1024,1024]

    void *p_dwq, *p_dwk, *p_dwv, *p_q, *p_k, *p_v, *p_attn, *p_out0;
    void *p_wqT, *p_wkT, *p_wvT;
    cudaGetSymbolAddress(&p_dwq, g_dwq);
    cudaGetSymbolAddress(&p_dwk, g_dwk);
    cudaGetSymbolAddress(&p_dwv, g_dwv);
    cudaGetSymbolAddress(&p_q,   g_q);
    cudaGetSymbolAddress(&p_k,   g_k);
    cudaGetSymbolAddress(&p_v,   g_v);
    cudaGetSymbolAddress(&p_attn, g_attn);
    cudaGetSymbolAddress(&p_out0, g_out0);
    cudaGetSymbolAddress(&p_wqT, g_wqT);
    cudaGetSymbolAddress(&p_wkT, g_wkT);
    cudaGetSymbolAddress(&p_wvT, g_wvT);

    static int smem_set = 0;
    if (!smem_set) {
        cudaFuncSetAttribute(fused_gate_attn1,
                             cudaFuncAttributeMaxDynamicSharedMemorySize, 8*3*N_*4*2);
        smem_set = 1;
    }

    transpose_w<<<dim3(8, 8),  dim3(32,8)>>>(qa_pw_w, (float*)p_wqT, 256);
    transpose_w<<<dim3(32, 8), dim3(32,8)>>>(ka_pw_w, (float*)p_wkT, 1024);
    transpose_w<<<dim3(8, 8),  dim3(32,8)>>>(va_pw_w, (float*)p_wvT, 256);
    dw3_kernel<<<B_*C_, 256>>>(x, qa_dw_w, qa_dw_b, ka_dw_w, ka_dw_b, va_dw_w, va_dw_b);

    // pointwise GEMMs: all on tensor core now
    tgemm_nn<<<dim3(8, 2, B_), 256>>>((const float*)p_wqT, 0, 0, 256,
                                      (const float*)p_dwq, (size_t)C_*N_, N_,
                                      (float*)p_q, (size_t)C_*N_, N_,
                                      qa_pw_b, 1.f, C_);
    tgemm_nn<<<dim3(8, 8, B_), 256>>>((const float*)p_wkT, 0, 0, 1024,
                                      (const float*)p_dwk, (size_t)C_*N_, N_,
                                      (float*)p_k, (size_t)EXP_*C_*N_, N_,
                                      ka_pw_b, 1.f, C_);
    tgemm_nn<<<dim3(8, 2, B_), 256>>>((const float*)p_wvT, 0, 0, 256,
                                      (const float*)p_dwv, (size_t)C_*N_, N_,
                                      (float*)p_v, (size_t)C_*N_, N_,
                                      va_pw_b, 1.f, C_);

    // qk on tensor core: attn[z][n][m] = 0.0625 * sum_c q[b][c][n]*k[z][c][m]
    tgemm_nn<<<dim3(8, 8, B_*EXP_), 256>>>((const float*)p_q, (size_t)C_*N_, 2, N_,
                                           (const float*)p_k, (size_t)C_*N_, N_,
                                           (float*)p_attn, (size_t)NN_, N_,
                                           nullptr, 0.0625f, C_);

    // FUSED conv0+BN+gate+conv1 -> second output
    fused_gate_attn1<<<dim3(N_/ROWS_, B_), 256, 8*3*N_*4*2>>>(
        attn0_w, bn_g, bn_b, bn_m, bn_v, attn1_w, out_attn);

    // av on tensor core: out0[c][n] = sum_m v[c][m] * attnF[n][m]  (both K-minor)
    tgemm_tt<<<dim3(8, 2, B_), 256>>>((const float*)p_v, (size_t)C_*N_, N_,
                                      out_attn, (size_t)NN_, N_,
                                      (float*)p_out0, (size_t)C_*N_, N_, N_);

    // proj 3x3 conv -> first output
    proj_kernel<<<dim3(64, B_), 256>>>(proj_w, out_main);
}

// round 16
// speedup vs baseline: 3.0688x; 2.5859x over previous
#include <cuda_runtime.h>
#include <cstddef>

#define B_   8
#define C_   256
#define N_   1024      // 32*32 spatial flattened
#define EXP_ 4
#define NN_  (N_*N_)
#define ROWS_ 16       // output rows per fused block

// ---------------- scratch (static device arrays; no runtime alloc) -----------
__device__ float g_dwq[B_*C_*N_];
__device__ float g_dwk[B_*C_*N_];
__device__ float g_dwv[B_*C_*N_];
__device__ float g_q  [B_*C_*N_];
__device__ float g_k  [B_*EXP_*C_*N_];
__device__ float g_v  [B_*C_*N_];
__device__ float g_attn [B_*EXP_*NN_];
__device__ float g_out0[B_*C_*N_];
__device__ float g_wqT[C_*C_];
__device__ float g_wkT[C_*EXP_*C_];
__device__ float g_wvT[C_*C_];
__device__ float g_pwT[9*C_*C_];        // proj weights [tap][ic][oc]

__device__ __forceinline__ float tf32r(float x) {
    float y;
    asm("cvt.rna.tf32.f32 %0, %1;" : "=f"(y) : "f"(x));
    return y;
}

#define MMA_TF32(acc, af, bf)                                                  \
    asm volatile(                                                              \
        "mma.sync.aligned.m16n8k8.row.col.f32.tf32.tf32.f32 "                  \
        "{%0,%1,%2,%3}, {%4,%5,%6,%7}, {%8,%9}, {%0,%1,%2,%3};"                \
        : "+f"((acc)[0]), "+f"((acc)[1]), "+f"((acc)[2]), "+f"((acc)[3])       \
        : "r"(__float_as_uint((af)[0])), "r"(__float_as_uint((af)[1])),        \
          "r"(__float_as_uint((af)[2])), "r"(__float_as_uint((af)[3])),        \
          "r"(__float_as_uint((bf)[0])), "r"(__float_as_uint((bf)[1])))

// ---------------- weight transpose: in [OC][256] -> out [256][OC] ------------
__global__ void transpose_w(const float* __restrict__ in, float* __restrict__ out, int OC)
{
    __shared__ float t[32][33];
    int oc0 = blockIdx.x * 32, c0 = blockIdx.y * 32;
    int x = threadIdx.x, y = threadIdx.y;
    for (int i = y; i < 32; i += 8) t[i][x] = in[(size_t)(oc0+i)*C_ + c0 + x];
    __syncthreads();
    for (int i = y; i < 32; i += 8) out[(size_t)(c0+i)*OC + oc0 + x] = t[x][i];
}

// ------------- proj weight transpose: [oc][ic][9] -> [t][ic][oc] -------------
__global__ void transpose_pw(const float* __restrict__ in, float* __restrict__ out)
{
    int idx = blockIdx.x * 256 + threadIdx.x;
    if (idx < 9*C_*C_) {
        int t = idx / (C_*C_); int r = idx % (C_*C_);
        int ic = r / C_; int oc = r % C_;
        out[idx] = in[((size_t)oc*C_ + ic)*9 + t];
    }
}

// ---------------- K1: fused 3-branch depthwise 3x3 + bias --------------------
__global__ void dw3_kernel(const float* __restrict__ x,
                           const float* __restrict__ wq, const float* __restrict__ bq,
                           const float* __restrict__ wk, const float* __restrict__ bk,
                           const float* __restrict__ wv, const float* __restrict__ bv)
{
    __shared__ float plane[N_];
    int bc = blockIdx.x; int b = bc >> 8, c = bc & 255;
    const float* src = x + ((size_t)(b*C_ + c))*N_;
    int tid = threadIdx.x;
    for (int i = tid; i < N_; i += 256) plane[i] = src[i];
    __syncthreads();
    float wwq[9], wwk[9], wwv[9];
    #pragma unroll
    for (int t = 0; t < 9; t++) { wwq[t]=wq[c*9+t]; wwk[t]=wk[c*9+t]; wwv[t]=wv[c*9+t]; }
    float bbq = bq[c], bbk = bk[c], bbv = bv[c];
    for (int i = tid; i < N_; i += 256) {
        int h = i >> 5, w = i & 31;
        float aq = bbq, ak = bbk, av = bbv;
        #pragma unroll
        for (int ky = 0; ky < 3; ky++) {
            int hh = h + ky - 1; if ((unsigned)hh >= 32u) continue;
            #pragma unroll
            for (int kx = 0; kx < 3; kx++) {
                int ww = w + kx - 1; if ((unsigned)ww >= 32u) continue;
                float in = plane[hh*32 + ww];
                aq += wwq[ky*3+kx]*in; ak += wwk[ky*3+kx]*in; av += wwv[ky*3+kx]*in;
            }
        }
        size_t o = ((size_t)(b*C_ + c))*N_ + i;
        g_dwq[o] = aq; g_dwk[o] = ak; g_dwv[o] = av;
    }
}

// ======== TENSOR-CORE tf32 GEMM, both operands K-major ("nn") ================
__global__ void __launch_bounds__(256) tgemm_nn(
    const float* __restrict__ A, size_t aBS, int aShift, int lda,
    const float* __restrict__ B, size_t bBS, int ldb,
    float* __restrict__ C, size_t cBS, int ldc,
    const float* __restrict__ bias, float alpha, int K)
{
    __shared__ float As[16][132];
    __shared__ float Bs[16][132];
    int z = blockIdx.z;
    const float* Ag = A + ((size_t)(z >> aShift))*aBS + blockIdx.y*128;
    const float* Bg = B + (size_t)z*bBS + blockIdx.x*128;
    int tid = threadIdx.x;
    int warp = tid >> 5, lane = tid & 31;
    int wm = warp >> 2, wn = warp & 3;
    int r  = lane >> 2, kk = lane & 3;

    int lr = tid >> 5, lc = (tid & 31) << 2;

    float4 a0 = *(const float4*)&Ag[(size_t)lr*lda + lc];
    float4 a1 = *(const float4*)&Ag[(size_t)(lr+8)*lda + lc];
    float4 b0 = *(const float4*)&Bg[(size_t)lr*ldb + lc];
    float4 b1 = *(const float4*)&Bg[(size_t)(lr+8)*ldb + lc];

    float acc[4][4][4];
    #pragma unroll
    for (int i = 0; i < 4; i++)
        #pragma unroll
        for (int j = 0; j < 4; j++)
            #pragma unroll
            for (int c = 0; c < 4; c++) acc[i][j][c] = 0.f;

    for (int k0 = 0; k0 < K; k0 += 16) {
        __syncthreads();
        As[lr][lc+0]=tf32r(a0.x); As[lr][lc+1]=tf32r(a0.y); As[lr][lc+2]=tf32r(a0.z); As[lr][lc+3]=tf32r(a0.w);
        As[lr+8][lc+0]=tf32r(a1.x); As[lr+8][lc+1]=tf32r(a1.y); As[lr+8][lc+2]=tf32r(a1.z); As[lr+8][lc+3]=tf32r(a1.w);
        Bs[lr][lc+0]=tf32r(b0.x); Bs[lr][lc+1]=tf32r(b0.y); Bs[lr][lc+2]=tf32r(b0.z); Bs[lr][lc+3]=tf32r(b0.w);
        Bs[lr+8][lc+0]=tf32r(b1.x); Bs[lr+8][lc+1]=tf32r(b1.y); Bs[lr+8][lc+2]=tf32r(b1.z); Bs[lr+8][lc+3]=tf32r(b1.w);
        __syncthreads();
        if (k0 + 16 < K) {
            a0 = *(const float4*)&Ag[(size_t)(k0+16+lr)*lda + lc];
            a1 = *(const float4*)&Ag[(size_t)(k0+24+lr)*lda + lc];
            b0 = *(const float4*)&Bg[(size_t)(k0+16+lr)*ldb + lc];
            b1 = *(const float4*)&Bg[(size_t)(k0+24+lr)*ldb + lc];
        }
        #pragma unroll
        for (int ks = 0; ks < 16; ks += 8) {
            float af[4][4]; float bf[4][2];
            #pragma unroll
            for (int mt = 0; mt < 4; mt++) {
                int m0 = wm*64 + mt*16;
                af[mt][0] = As[ks+kk  ][m0 + r];
                af[mt][1] = As[ks+kk  ][m0 + r + 8];
                af[mt][2] = As[ks+kk+4][m0 + r];
                af[mt][3] = As[ks+kk+4][m0 + r + 8];
            }
            #pragma unroll
            for (int nt = 0; nt < 4; nt++) {
                int n0 = wn*32 + nt*8;
                bf[nt][0] = Bs[ks+kk  ][n0 + r];
                bf[nt][1] = Bs[ks+kk+4][n0 + r];
            }
            #pragma unroll
            for (int mt = 0; mt < 4; mt++)
                #pragma unroll
                for (int nt = 0; nt < 4; nt++)
                    MMA_TF32(acc[mt][nt], af[mt], bf[nt]);
        }
    }
    float* Cg = C + (size_t)z*cBS;
    int mW = blockIdx.y*128 + wm*64, nW = blockIdx.x*128 + wn*32;
    #pragma unroll
    for (int mt = 0; mt < 4; mt++) {
        int m0 = mW + mt*16 + r;
        int m1 = m0 + 8;
        float bi0 = bias ? bias[m0] : 0.f;
        float bi1 = bias ? bias[m1] : 0.f;
        #pragma unroll
        for (int nt = 0; nt < 4; nt++) {
            int n0 = nW + nt*8 + 2*kk;
            float2 o0 = make_float2(acc[mt][nt][0]*alpha + bi0, acc[mt][nt][1]*alpha + bi0);
            float2 o1 = make_float2(acc[mt][nt][2]*alpha + bi1, acc[mt][nt][3]*alpha + bi1);
            *(float2*)&Cg[(size_t)m0*ldc + n0] = o0;
            *(float2*)&Cg[(size_t)m1*ldc + n0] = o1;
        }
    }
}

// ======== TENSOR-CORE tf32 GEMM, both operands K-minor ("tt") ================
__global__ void __launch_bounds__(256) tgemm_tt(
    const float* __restrict__ A, size_t aBS, int lda,
    const float* __restrict__ B, size_t bBS, int ldb,
    float* __restrict__ C, size_t cBS, int ldc, int K)
{
    __shared__ float As[16][132];
    __shared__ float Bs[16][132];
    int z = blockIdx.z;
    const float* Ag = A + (size_t)z*aBS + (size_t)(blockIdx.y*128)*lda;
    const float* Bg = B + (size_t)z*bBS + (size_t)(blockIdx.x*128)*ldb;
    int tid = threadIdx.x;
    int warp = tid >> 5, lane = tid & 31;
    int wm = warp >> 2, wn = warp & 3;
    int r  = lane >> 2, kk = lane & 3;
    int r0 = tid >> 2, c0 = (tid & 3) << 2;

    float4 a0 = *(const float4*)&Ag[(size_t)r0*lda + c0];
    float4 a1 = *(const float4*)&Ag[(size_t)(r0+64)*lda + c0];
    float4 b0 = *(const float4*)&Bg[(size_t)r0*ldb + c0];
    float4 b1 = *(const float4*)&Bg[(size_t)(r0+64)*ldb + c0];

    float acc[4][4][4];
    #pragma unroll
    for (int i = 0; i < 4; i++)
        #pragma unroll
        for (int j = 0; j < 4; j++)
            #pragma unroll
            for (int c = 0; c < 4; c++) acc[i][j][c] = 0.f;

    for (int k0 = 0; k0 < K; k0 += 16) {
        __syncthreads();
        As[c0+0][r0]=tf32r(a0.x); As[c0+1][r0]=tf32r(a0.y); As[c0+2][r0]=tf32r(a0.z); As[c0+3][r0]=tf32r(a0.w);
        As[c0+0][r0+64]=tf32r(a1.x); As[c0+1][r0+64]=tf32r(a1.y); As[c0+2][r0+64]=tf32r(a1.z); As[c0+3][r0+64]=tf32r(a1.w);
        Bs[c0+0][r0]=tf32r(b0.x); Bs[c0+1][r0]=tf32r(b0.y); Bs[c0+2][r0]=tf32r(b0.z); Bs[c0+3][r0]=tf32r(b0.w);
        Bs[c0+0][r0+64]=tf32r(b1.x); Bs[c0+1][r0+64]=tf32r(b1.y); Bs[c0+2][r0+64]=tf32r(b1.z); Bs[c0+3][r0+64]=tf32r(b1.w);
        __syncthreads();
        if (k0 + 16 < K) {
            a0 = *(const float4*)&Ag[(size_t)r0*lda + k0+16 + c0];
            a1 = *(const float4*)&Ag[(size_t)(r0+64)*lda + k0+16 + c0];
            b0 = *(const float4*)&Bg[(size_t)r0*ldb + k0+16 + c0];
            b1 = *(const float4*)&Bg[(size_t)(r0+64)*ldb + k0+16 + c0];
        }
        #pragma unroll
        for (int ks = 0; ks < 16; ks += 8) {
            float af[4][4]; float bf[4][2];
            #pragma unroll
            for (int mt = 0; mt < 4; mt++) {
                int m0 = wm*64 + mt*16;
                af[mt][0] = As[ks+kk  ][m0 + r];
                af[mt][1] = As[ks+kk  ][m0 + r + 8];
                af[mt][2] = As[ks+kk+4][m0 + r];
                af[mt][3] = As[ks+kk+4][m0 + r + 8];
            }
            #pragma unroll
            for (int nt = 0; nt < 4; nt++) {
                int n0 = wn*32 + nt*8;
                bf[nt][0] = Bs[ks+kk  ][n0 + r];
                bf[nt][1] = Bs[ks+kk+4][n0 + r];
            }
            #pragma unroll
            for (int mt = 0; mt < 4; mt++)
                #pragma unroll
                for (int nt = 0; nt < 4; nt++)
                    MMA_TF32(acc[mt][nt], af[mt], bf[nt]);
        }
    }
    float* Cg = C + (size_t)z*cBS;
    int mW = blockIdx.y*128 + wm*64, nW = blockIdx.x*128 + wn*32;
    #pragma unroll
    for (int mt = 0; mt < 4; mt++) {
        int m0 = mW + mt*16 + r;
        int m1 = m0 + 8;
        #pragma unroll
        for (int nt = 0; nt < 4; nt++) {
            int n0 = nW + nt*8 + 2*kk;
            *(float2*)&Cg[(size_t)m0*ldc + n0] = make_float2(acc[mt][nt][0], acc[mt][nt][1]);
            *(float2*)&Cg[(size_t)m1*ldc + n0] = make_float2(acc[mt][nt][2], acc[mt][nt][3]);
        }
    }
}

// ======== K7: proj 3x3 conv as tensor-core implicit GEMM =====================
// out[b][oc][n] = sum_t sum_ic pwT[t][ic][oc] * in[b][ic][n+off_t] (masked)
// 9 taps x 16 k-steps accumulated into one register tile.
__global__ void __launch_bounds__(256) tproj(
    const float* __restrict__ pwT, float* __restrict__ dst)
{
    __shared__ float As[16][132];
    __shared__ float Bs[16][132];
    int b = blockIdx.z;
    int mBase = blockIdx.y*128;   // oc
    int nBase = blockIdx.x*128;   // n
    int tid = threadIdx.x;
    int warp = tid >> 5, lane = tid & 31;
    int wm = warp >> 2, wn = warp & 3;
    int r  = lane >> 2, kk = lane & 3;
    int lr = tid >> 5, lc = (tid & 31) << 2;

    const float* Bbase = g_out0 + (size_t)b*C_*N_;

    // per-thread loader helpers for iteration it = t*16 + (k0/16)
    auto loadAB = [&](int it, float4& a0, float4& a1, float4& b0v, float4& b1v) {
        int t  = it >> 4;
        int k0 = (it & 15) << 4;
        int dy = t/3 - 1, dx = t%3 - 1;
        int off = dy*32 + dx;
        const float* Ag = pwT + ((size_t)t*C_ + k0)*C_ + mBase;
        a0 = *(const float4*)&Ag[(size_t)lr*C_ + lc];
        a1 = *(const float4*)&Ag[(size_t)(lr+8)*C_ + lc];
        float bv[2][4];
        #pragma unroll
        for (int i = 0; i < 4; i++) {
            int col = nBase + lc + i;
            int h = col >> 5, w = col & 31;
            bool ok = ((unsigned)(h+dy) < 32u) && ((unsigned)(w+dx) < 32u);
            int src = col + off;
            bv[0][i] = ok ? Bbase[(size_t)(k0+lr  )*N_ + src] : 0.f;
            bv[1][i] = ok ? Bbase[(size_t)(k0+lr+8)*N_ + src] : 0.f;
        }
        b0v = make_float4(bv[0][0], bv[0][1], bv[0][2], bv[0][3]);
        b1v = make_float4(bv[1][0], bv[1][1], bv[1][2], bv[1][3]);
    };

    float4 a0, a1, b0, b1;
    loadAB(0, a0, a1, b0, b1);

    float acc[4][4][4];
    #pragma unroll
    for (int i = 0; i < 4; i++)
        #pragma unroll
        for (int j = 0; j < 4; j++)
            #pragma unroll
            for (int c = 0; c < 4; c++) acc[i][j][c] = 0.f;

    const int NIT = 9*16;
    for (int it = 0; it < NIT; it++) {
        __syncthreads();
        As[lr][lc+0]=tf32r(a0.x); As[lr][lc+1]=tf32r(a0.y); As[lr][lc+2]=tf32r(a0.z); As[lr][lc+3]=tf32r(a0.w);
        As[lr+8][lc+0]=tf32r(a1.x); As[lr+8][lc+1]=tf32r(a1.y); As[lr+8][lc+2]=tf32r(a1.z); As[lr+8][lc+3]=tf32r(a1.w);
        Bs[lr][lc+0]=tf32r(b0.x); Bs[lr][lc+1]=tf32r(b0.y); Bs[lr][lc+2]=tf32r(b0.z); Bs[lr][lc+3]=tf32r(b0.w);
        Bs[lr+8][lc+0]=tf32r(b1.x); Bs[lr+8][lc+1]=tf32r(b1.y); Bs[lr+8][lc+2]=tf32r(b1.z); Bs[lr+8][lc+3]=tf32r(b1.w);
        __syncthreads();
        if (it + 1 < NIT) loadAB(it + 1, a0, a1, b0, b1);
        #pragma unroll
        for (int ks = 0; ks < 16; ks += 8) {
            float af[4][4]; float bf[4][2];
            #pragma unroll
            for (int mt = 0; mt < 4; mt++) {
                int m0 = wm*64 + mt*16;
                af[mt][0] = As[ks+kk  ][m0 + r];
                af[mt][1] = As[ks+kk  ][m0 + r + 8];
                af[mt][2] = As[ks+kk+4][m0 + r];
                af[mt][3] = As[ks+kk+4][m0 + r + 8];
            }
            #pragma unroll
            for (int nt = 0; nt < 4; nt++) {
                int n0 = wn*32 + nt*8;
                bf[nt][0] = Bs[ks+kk  ][n0 + r];
                bf[nt][1] = Bs[ks+kk+4][n0 + r];
            }
            #pragma unroll
            for (int mt = 0; mt < 4; mt++)
                #pragma unroll
                for (int nt = 0; nt < 4; nt++)
                    MMA_TF32(acc[mt][nt], af[mt], bf[nt]);
        }
    }
    float* Cg = dst + (size_t)b*C_*N_;
    int mW = mBase + wm*64, nW = nBase + wn*32;
    #pragma unroll
    for (int mt = 0; mt < 4; mt++) {
        int m0 = mW + mt*16 + r;
        int m1 = m0 + 8;
        #pragma unroll
        for (int nt = 0; nt < 4; nt++) {
            int n0 = nW + nt*8 + 2*kk;
            *(float2*)&Cg[(size_t)m0*N_ + n0] = make_float2(acc[mt][nt][0], acc[mt][nt][1]);
            *(float2*)&Cg[(size_t)m1*N_ + n0] = make_float2(acc[mt][nt][2], acc[mt][nt][3]);
        }
    }
}

// ======= K45: FUSED conv0(4->4)+BN + self-gated softmax + conv1(4->1) ========
__global__ void __launch_bounds__(256) fused_gate_attn1(
    const float* __restrict__ w0,
    const float* __restrict__ gma, const float* __restrict__ bta,
    const float* __restrict__ mu,  const float* __restrict__ var,
    const float* __restrict__ w1,  float* __restrict__ dst)
{
    extern __shared__ float sm[];
    float* attn_s  = sm;                 // [4][3][N_]
    float* gated_s = sm + 4*3*N_;        // [4][3][N_]
    __shared__ float wsm[144];
    __shared__ float w1sm[36];
    __shared__ float redM[8][4];
    __shared__ float redS[8][4];

    int b = blockIdx.y;
    int r0 = blockIdx.x * ROWS_;
    int tid = threadIdx.x;
    int lane = tid & 31, wid = tid >> 5;

    if (tid < 144) wsm[tid] = w0[tid];
    if (tid < 36)  w1sm[tid] = w1[tid];
    float sc[4], sh[4];
    #pragma unroll
    for (int f = 0; f < 4; f++) {
        float inv = rsqrtf(var[f] + 1e-5f);
        sc[f] = gma[f] * inv; sh[f] = bta[f] - mu[f] * sc[f];
    }

    #define SLOT(r)  (((r) + 3072) % 3)
    #define ATT(e,s,m)   attn_s [(((e)*3)+(s))*N_ + (m)]
    #define GAT(f,s,m)   gated_s[(((f)*3)+(s))*N_ + (m)]

    for (int rr = r0-2; rr <= r0; rr++) {
        int s = SLOT(rr);
        bool ok = (unsigned)rr < (unsigned)N_;
        #pragma unroll
        for (int e = 0; e < 4; e++) {
            float4 v = ok ? *(const float4*)&g_attn[(((size_t)(b*4+e))*N_ + rr)*N_ + tid*4]
                          : make_float4(0.f,0.f,0.f,0.f);
            *(float4*)&ATT(e, s, tid*4) = v;
        }
    }
    __syncthreads();

    for (int g = r0-1; g <= r0+ROWS_; g++) {
        int s1 = SLOT(g);
        if ((unsigned)g < (unsigned)N_) {
            int srow[3] = {SLOT(g-1), s1, SLOT(g+1)};
            float acc[4][4] = {};
            #pragma unroll
            for (int e = 0; e < 4; e++) {
                #pragma unroll
                for (int t = 0; t < 9; t++) {
                    int ky = t/3, kx = t%3;
                    float w0r = wsm[(0*4+e)*9+t], w1r = wsm[(1*4+e)*9+t];
                    float w2r = wsm[(2*4+e)*9+t], w3r = wsm[(3*4+e)*9+t];
                    #pragma unroll
                    for (int j = 0; j < 4; j++) {
                        int m = tid + 256*j + kx - 1;
                        float in = ((unsigned)m < (unsigned)N_) ? ATT(e, srow[ky], m) : 0.f;
                        acc[0][j] += w0r*in; acc[1][j] += w1r*in;
                        acc[2][j] += w2r*in; acc[3][j] += w3r*in;
                    }
                }
            }
            #pragma unroll
            for (int f = 0; f < 4; f++)
                #pragma unroll
                for (int j = 0; j < 4; j++) acc[f][j] = acc[f][j]*sc[f] + sh[f];

            float mx[4];
            #pragma unroll
            for (int f = 0; f < 4; f++)
                mx[f] = fmaxf(fmaxf(acc[f][0], acc[f][1]), fmaxf(acc[f][2], acc[f][3]));
            #pragma unroll
            for (int o = 16; o > 0; o >>= 1)
                #pragma unroll
                for (int f = 0; f < 4; f++)
                    mx[f] = fmaxf(mx[f], __shfl_xor_sync(0xffffffffu, mx[f], o));
            if (lane == 0) { redM[wid][0]=mx[0]; redM[wid][1]=mx[1]; redM[wid][2]=mx[2]; redM[wid][3]=mx[3]; }
            __syncthreads();
            float M[4];
            #pragma unroll
            for (int f = 0; f < 4; f++) {
                float v = redM[0][f];
                #pragma unroll
                for (int w = 1; w < 8; w++) v = fmaxf(v, redM[w][f]);
                M[f] = v;
            }
            float es[4][4], ps[4] = {0.f,0.f,0.f,0.f};
            #pragma unroll
            for (int f = 0; f < 4; f++)
                #pragma unroll
                for (int j = 0; j < 4; j++) { es[f][j] = __expf(acc[f][j] - M[f]); ps[f] += es[f][j]; }
            #pragma unroll
            for (int o = 16; o > 0; o >>= 1)
                #pragma unroll
                for (int f = 0; f < 4; f++)
                    ps[f] += __shfl_xor_sync(0xffffffffu, ps[f], o);
            if (lane == 0) { redS[wid][0]=ps[0]; redS[wid][1]=ps[1]; redS[wid][2]=ps[2]; redS[wid][3]=ps[3]; }
            __syncthreads();
            float invS[4];
            #pragma unroll
            for (int f = 0; f < 4; f++) {
                float v = 0.f;
                #pragma unroll
                for (int w = 0; w < 8; w++) v += redS[w][f];
                invS[f] = 1.f / v;
            }
            #pragma unroll
            for (int f = 0; f < 4; f++)
                #pragma unroll
                for (int j = 0; j < 4; j++)
                    GAT(f, s1, tid + 256*j) = acc[f][j] * es[f][j] * invS[f];
        } else {
            #pragma unroll
            for (int f = 0; f < 4; f++)
                #pragma unroll
                for (int j = 0; j < 4; j++) GAT(f, s1, tid + 256*j) = 0.f;
        }
        __syncthreads();

        if (g >= r0+1) {
            int n = g-1;
            int trow[3] = {SLOT(n-1), SLOT(n), SLOT(n+1)};
            float acc2[4] = {};
            #pragma unroll
            for (int e = 0; e < 4; e++)
                #pragma unroll
                for (int t = 0; t < 9; t++) {
                    int ky = t/3, kx = t%3;
                    float wv = w1sm[e*9 + t];
                    #pragma unroll
                    for (int j = 0; j < 4; j++) {
                        int m = tid + 256*j + kx - 1;
                        float in = ((unsigned)m < (unsigned)N_) ? GAT(e, trow[ky], m) : 0.f;
                        acc2[j] += wv*in;
                    }
                }
            #pragma unroll
            for (int j = 0; j < 4; j++)
                dst[((size_t)b*N_ + n)*N_ + tid + 256*j] = acc2[j];
        }

        if (g < r0+ROWS_) {
            int rr = g+2; int s = SLOT(rr);
            bool ok = (unsigned)rr < (unsigned)N_;
            #pragma unroll
            for (int e = 0; e < 4; e++) {
                float4 v = ok ? *(const float4*)&g_attn[(((size_t)(b*4+e))*N_ + rr)*N_ + tid*4]
                              : make_float4(0.f,0.f,0.f,0.f);
                *(float4*)&ATT(e, s, tid*4) = v;
            }
        }
        __syncthreads();
    }
    #undef SLOT
    #undef ATT
    #undef GAT
}

// ---------------------------------------------------------------------------
extern "C" void kernel_launch(void* const* d_in, const int* in_sizes, int n_in,
                              void* d_out, int out_size)
{
    const float* x       = (const float*)d_in[0];
    const float* qa_dw_w = (const float*)d_in[1];
    const float* qa_dw_b = (const float*)d_in[2];
    const float* qa_pw_w = (const float*)d_in[3];
    const float* qa_pw_b = (const float*)d_in[4];
    const float* ka_dw_w = (const float*)d_in[5];
    const float* ka_dw_b = (const float*)d_in[6];
    const float* ka_pw_w = (const float*)d_in[7];
    const float* ka_pw_b = (const float*)d_in[8];
    const float* va_dw_w = (const float*)d_in[9];
    const float* va_dw_b = (const float*)d_in[10];
    const float* va_pw_w = (const float*)d_in[11];
    const float* va_pw_b = (const float*)d_in[12];
    const float* attn0_w = (const float*)d_in[13];
    const float* bn_g    = (const float*)d_in[14];
    const float* bn_b    = (const float*)d_in[15];
    const float* bn_m    = (const float*)d_in[16];
    const float* bn_v    = (const float*)d_in[17];
    const float* attn1_w = (const float*)d_in[18];
    const float* proj_w  = (const float*)d_in[19];

    float* out_main = (float*)d_out;                 // [8,256,32,32]
    float* out_attn = out_main + (size_t)B_*C_*N_;   // [8,1,1024,1024]

    void *p_dwq, *p_dwk, *p_dwv, *p_q, *p_k, *p_v, *p_attn, *p_out0;
    void *p_wqT, *p_wkT, *p_wvT, *p_pwT;
    cudaGetSymbolAddress(&p_dwq, g_dwq);
    cudaGetSymbolAddress(&p_dwk, g_dwk);
    cudaGetSymbolAddress(&p_dwv, g_dwv);
    cudaGetSymbolAddress(&p_q,   g_q);
    cudaGetSymbolAddress(&p_k,   g_k);
    cudaGetSymbolAddress(&p_v,   g_v);
    cudaGetSymbolAddress(&p_attn, g_attn);
    cudaGetSymbolAddress(&p_out0, g_out0);
    cudaGetSymbolAddress(&p_wqT, g_wqT);
    cudaGetSymbolAddress(&p_wkT, g_wkT);
    cudaGetSymbolAddress(&p_wvT, g_wvT);
    cudaGetSymbolAddress(&p_pwT, g_pwT);

    static int smem_set = 0;
    if (!smem_set) {
        cudaFuncSetAttribute(fused_gate_attn1,
                             cudaFuncAttributeMaxDynamicSharedMemorySize, 8*3*N_*4*2);
        smem_set = 1;
    }

    transpose_w<<<dim3(8, 8),  dim3(32,8)>>>(qa_pw_w, (float*)p_wqT, 256);
    transpose_w<<<dim3(32, 8), dim3(32,8)>>>(ka_pw_w, (float*)p_wkT, 1024);
    transpose_w<<<dim3(8, 8),  dim3(32,8)>>>(va_pw_w, (float*)p_wvT, 256);
    transpose_pw<<<(9*C_*C_+255)/256, 256>>>(proj_w, (float*)p_pwT);
    dw3_kernel<<<B_*C_, 256>>>(x, qa_dw_w, qa_dw_b, ka_dw_w, ka_dw_b, va_dw_w, va_dw_b);

    // pointwise GEMMs: all on tensor core
    tgemm_nn<<<dim3(8, 2, B_), 256>>>((const float*)p_wqT, 0, 0, 256,
                                      (const float*)p_dwq, (size_t)C_*N_, N_,
                                      (float*)p_q, (size_t)C_*N_, N_,
                                      qa_pw_b, 1.f, C_);
    tgemm_nn<<<dim3(8, 8, B_), 256>>>((const float*)p_wkT, 0, 0, 1024,
                                      (const float*)p_dwk, (size_t)C_*N_, N_,
                                      (float*)p_k, (size_t)EXP_*C_*N_, N_,
                                      ka_pw_b, 1.f, C_);
    tgemm_nn<<<dim3(8, 2, B_), 256>>>((const float*)p_wvT, 0, 0, 256,
                                      (const float*)p_dwv, (size_t)C_*N_, N_,
                                      (float*)p_v, (size_t)C_*N_, N_,
                                      va_pw_b, 1.f, C_);

    // qk on tensor core: attn[z][n][m] = 0.0625 * sum_c q[b][c][n]*k[z][c][m]
    tgemm_nn<<<dim3(8, 8, B_*EXP_), 256>>>((const float*)p_q, (size_t)C_*N_, 2, N_,
                                           (const float*)p_k, (size_t)C_*N_, N_,
                                           (float*)p_attn, (size_t)NN_, N_,
                                           nullptr, 0.0625f, C_);

    // FUSED conv0+BN+gate+conv1 -> second output
    fused_gate_attn1<<<dim3(N_/ROWS_, B_), 256, 8*3*N_*4*2>>>(
        attn0_w, bn_g, bn_b, bn_m, bn_v, attn1_w, out_attn);

    // av on tensor core: out0[c][n] = sum_m v[c][m] * attnF[n][m]
    tgemm_tt<<<dim3(8, 2, B_), 256>>>((const float*)p_v, (size_t)C_*N_, N_,
                                      out_attn, (size_t)NN_, N_,
                                      (float*)p_out0, (size_t)C_*N_, N_, N_);

    // proj conv as tensor-core implicit GEMM -> first output
    tproj<<<dim3(8, 2, B_), 256>>>((const float*)p_pwT, out_main);
}